// round 1
// baseline (speedup 1.0000x reference)
#include <cuda_runtime.h>
#include <math.h>

#define BATCH 2
#define LA 4096
#define LB 4096
#define EMB 1024
#define HID 1024
#define MTOT (BATCH * LA)  // 8192 rows for the shared-weight MLP

// ---------------- scratch (device globals: no alloc allowed) ----------------
__device__ float g_t1[(size_t)MTOT * HID];
__device__ float g_t2[(size_t)MTOT * HID];
__device__ float g_fa[(size_t)MTOT * HID];
__device__ float g_fb[(size_t)MTOT * HID];
__device__ float g_S[(size_t)BATCH * LA * LB];
__device__ float g_mrow[BATCH * LA];
__device__ float g_izrow[BATCH * LA];
__device__ float g_mcol[BATCH * LB];
__device__ float g_izcol[BATCH * LB];

// ---------------- shared inner product: 128x128x16 tile, 8x8/thread ----------
#define INNER_LOOP()                                                        \
  _Pragma("unroll")                                                         \
  for (int kk = 0; kk < 16; kk++) {                                         \
    float a[8], bfr[8];                                                     \
    *(float4*)&a[0]   = *(float4*)&As[kk][ty * 8];                          \
    *(float4*)&a[4]   = *(float4*)&As[kk][ty * 8 + 4];                      \
    *(float4*)&bfr[0] = *(float4*)&Bs[kk][tx * 8];                          \
    *(float4*)&bfr[4] = *(float4*)&Bs[kk][tx * 8 + 4];                      \
    _Pragma("unroll") for (int i = 0; i < 8; i++)                           \
      _Pragma("unroll") for (int j = 0; j < 8; j++)                         \
        acc[i][j] += a[i] * bfr[j];                                         \
  }

// ---------------- GEMM: C = relu(A @ W + b), A[M,K], W[K,N] -----------------
__global__ __launch_bounds__(256) void gemm_bias_relu(
    const float* __restrict__ A, const float* __restrict__ W,
    const float* __restrict__ bias, float* __restrict__ C,
    int M, int N, int K) {
  __shared__ float As[16][128];
  __shared__ float Bs[16][128];
  const int tid = threadIdx.x;
  const int tx = tid & 15, ty = tid >> 4;
  const int bm = blockIdx.y * 128, bn = blockIdx.x * 128;
  const int ar = tid >> 2, ac = (tid & 3) << 2;   // A transpose loader
  const int br = tid >> 4, bc = (tid & 15) << 2;  // B direct loader
  float acc[8][8] = {};
  for (int k0 = 0; k0 < K; k0 += 16) {
    float4 a0 = *(const float4*)(A + (size_t)(bm + ar) * K + k0 + ac);
    float4 a1 = *(const float4*)(A + (size_t)(bm + ar + 64) * K + k0 + ac);
    As[ac + 0][ar] = a0.x; As[ac + 1][ar] = a0.y;
    As[ac + 2][ar] = a0.z; As[ac + 3][ar] = a0.w;
    As[ac + 0][ar + 64] = a1.x; As[ac + 1][ar + 64] = a1.y;
    As[ac + 2][ar + 64] = a1.z; As[ac + 3][ar + 64] = a1.w;
    const float* Wr = W + (size_t)(k0 + br) * N + bn;
    *(float4*)&Bs[br][bc]      = *(const float4*)(Wr + bc);
    *(float4*)&Bs[br][bc + 64] = *(const float4*)(Wr + bc + 64);
    __syncthreads();
    INNER_LOOP();
    __syncthreads();
  }
#pragma unroll
  for (int i = 0; i < 8; i++) {
    float* Cr = C + (size_t)(bm + ty * 8 + i) * N + bn + tx * 8;
#pragma unroll
    for (int j = 0; j < 8; j += 4) {
      float4 v;
      v.x = fmaxf(acc[i][j + 0] + bias[bn + tx * 8 + j + 0], 0.f);
      v.y = fmaxf(acc[i][j + 1] + bias[bn + tx * 8 + j + 1], 0.f);
      v.z = fmaxf(acc[i][j + 2] + bias[bn + tx * 8 + j + 2], 0.f);
      v.w = fmaxf(acc[i][j + 3] + bias[bn + tx * 8 + j + 3], 0.f);
      *(float4*)(Cr + j) = v;
    }
  }
}

// ---------------- scores: S[b] = fa[b] @ fb[b]^T -----------------------------
__global__ __launch_bounds__(256) void scores_gemm() {
  const int b = blockIdx.z;
  const float* A  = g_fa + (size_t)b * LA * HID;
  const float* Bm = g_fb + (size_t)b * LB * HID;
  float* C = g_S + (size_t)b * LA * LB;
  __shared__ float As[16][128];
  __shared__ float Bs[16][128];
  const int tid = threadIdx.x;
  const int tx = tid & 15, ty = tid >> 4;
  const int bm = blockIdx.y * 128, bn = blockIdx.x * 128;
  const int ar = tid >> 2, ac = (tid & 3) << 2;
  float acc[8][8] = {};
  for (int k0 = 0; k0 < HID; k0 += 16) {
    float4 a0 = *(const float4*)(A + (size_t)(bm + ar) * HID + k0 + ac);
    float4 a1 = *(const float4*)(A + (size_t)(bm + ar + 64) * HID + k0 + ac);
    As[ac + 0][ar] = a0.x; As[ac + 1][ar] = a0.y;
    As[ac + 2][ar] = a0.z; As[ac + 3][ar] = a0.w;
    As[ac + 0][ar + 64] = a1.x; As[ac + 1][ar + 64] = a1.y;
    As[ac + 2][ar + 64] = a1.z; As[ac + 3][ar + 64] = a1.w;
    float4 b0 = *(const float4*)(Bm + (size_t)(bn + ar) * HID + k0 + ac);
    float4 b1 = *(const float4*)(Bm + (size_t)(bn + ar + 64) * HID + k0 + ac);
    Bs[ac + 0][ar] = b0.x; Bs[ac + 1][ar] = b0.y;
    Bs[ac + 2][ar] = b0.z; Bs[ac + 3][ar] = b0.w;
    Bs[ac + 0][ar + 64] = b1.x; Bs[ac + 1][ar + 64] = b1.y;
    Bs[ac + 2][ar + 64] = b1.z; Bs[ac + 3][ar + 64] = b1.w;
    __syncthreads();
    INNER_LOOP();
    __syncthreads();
  }
#pragma unroll
  for (int i = 0; i < 8; i++) {
    float* Cr = C + (size_t)(bm + ty * 8 + i) * LB + bn + tx * 8;
    *(float4*)(Cr + 0) = *(float4*)&acc[i][0];
    *(float4*)(Cr + 4) = *(float4*)&acc[i][4];
  }
}

// ---------------- online (max, sumexp) combine -------------------------------
__device__ __forceinline__ void olcomb(float& m, float& z, float m2, float z2) {
  if (m2 > m) { z = z * __expf(m - m2) + z2; m = m2; }
  else        { z = z + z2 * __expf(m2 - m); }
}

// ---------------- row stats: max_j, sum_j exp --------------------------------
__global__ void row_stats_kernel() {
  const int row = blockIdx.x;  // 0..BATCH*LA-1
  const float* s = g_S + (size_t)row * LB;
  float m = -3.0e38f, z = 0.f;
  for (int j = threadIdx.x; j < LB; j += 256) {
    float v = s[j];
    if (v > m) { z = z * __expf(m - v) + 1.f; m = v; }
    else       { z += __expf(v - m); }
  }
  __shared__ float sm[256], sz[256];
  sm[threadIdx.x] = m; sz[threadIdx.x] = z;
  __syncthreads();
  for (int st = 128; st > 0; st >>= 1) {
    if (threadIdx.x < st) {
      float m1 = sm[threadIdx.x], z1 = sz[threadIdx.x];
      olcomb(m1, z1, sm[threadIdx.x + st], sz[threadIdx.x + st]);
      sm[threadIdx.x] = m1; sz[threadIdx.x] = z1;
    }
    __syncthreads();
  }
  if (threadIdx.x == 0) { g_mrow[row] = sm[0]; g_izrow[row] = 1.f / sz[0]; }
}

// ---------------- col stats: max_i, sum_i exp --------------------------------
__global__ void col_stats_kernel() {
  const int b = blockIdx.y;
  const int col = blockIdx.x * 128 + threadIdx.x;
  const float* s = g_S + (size_t)b * LA * LB + col;
  float m = -3.0e38f, z = 0.f;
  for (int i = threadIdx.y; i < LA; i += 8) {
    float v = s[(size_t)i * LB];
    if (v > m) { z = z * __expf(m - v) + 1.f; m = v; }
    else       { z += __expf(v - m); }
  }
  __shared__ float sm[8][128], sz[8][128];
  sm[threadIdx.y][threadIdx.x] = m; sz[threadIdx.y][threadIdx.x] = z;
  __syncthreads();
  if (threadIdx.y == 0) {
#pragma unroll
    for (int y = 1; y < 8; y++) olcomb(m, z, sm[y][threadIdx.x], sz[y][threadIdx.x]);
    g_mcol[b * LB + col] = m;
    g_izcol[b * LB + col] = 1.f / z;
  }
}

// ---------------- beta = rowsoftmax(S) @ x2 ----------------------------------
__global__ __launch_bounds__(256) void beta_gemm(const float* __restrict__ x2,
                                                 float* __restrict__ out) {
  const int b = blockIdx.z;
  const float* S = g_S + (size_t)b * LA * LB;
  const float* X = x2 + (size_t)b * LB * EMB;
  float* C = out + (size_t)b * LA * EMB;
  __shared__ float As[16][128];
  __shared__ float Bs[16][128];
  __shared__ float s_m[128], s_iz[128];
  const int tid = threadIdx.x;
  const int tx = tid & 15, ty = tid >> 4;
  const int bm = blockIdx.y * 128, bn = blockIdx.x * 128;
  if (tid < 128) {
    s_m[tid]  = g_mrow[b * LA + bm + tid];
    s_iz[tid] = g_izrow[b * LA + bm + tid];
  }
  __syncthreads();
  const int ar = tid >> 2, ac = (tid & 3) << 2;
  const int br = tid >> 4, bc = (tid & 15) << 2;
  const float m0 = s_m[ar], iz0 = s_iz[ar];
  const float m1 = s_m[ar + 64], iz1 = s_iz[ar + 64];
  float acc[8][8] = {};
  for (int k0 = 0; k0 < LB; k0 += 16) {
    float4 a0 = *(const float4*)(S + (size_t)(bm + ar) * LB + k0 + ac);
    float4 a1 = *(const float4*)(S + (size_t)(bm + ar + 64) * LB + k0 + ac);
    As[ac + 0][ar] = __expf(a0.x - m0) * iz0;
    As[ac + 1][ar] = __expf(a0.y - m0) * iz0;
    As[ac + 2][ar] = __expf(a0.z - m0) * iz0;
    As[ac + 3][ar] = __expf(a0.w - m0) * iz0;
    As[ac + 0][ar + 64] = __expf(a1.x - m1) * iz1;
    As[ac + 1][ar + 64] = __expf(a1.y - m1) * iz1;
    As[ac + 2][ar + 64] = __expf(a1.z - m1) * iz1;
    As[ac + 3][ar + 64] = __expf(a1.w - m1) * iz1;
    const float* Xr = X + (size_t)(k0 + br) * EMB + bn;
    *(float4*)&Bs[br][bc]      = *(const float4*)(Xr + bc);
    *(float4*)&Bs[br][bc + 64] = *(const float4*)(Xr + bc + 64);
    __syncthreads();
    INNER_LOOP();
    __syncthreads();
  }
#pragma unroll
  for (int i = 0; i < 8; i++) {
    float* Cr = C + (size_t)(bm + ty * 8 + i) * EMB + bn + tx * 8;
    *(float4*)(Cr + 0) = *(float4*)&acc[i][0];
    *(float4*)(Cr + 4) = *(float4*)&acc[i][4];
  }
}

// ---------------- alpha = colsoftmax(S)^T @ x1 -------------------------------
// alpha[j][e] = sum_i exp(S[i][j]-mcol[j])*izcol[j] * x1[i][e]
__global__ __launch_bounds__(256) void alpha_gemm(const float* __restrict__ x1,
                                                  float* __restrict__ out) {
  const int b = blockIdx.z;
  const float* S = g_S + (size_t)b * LA * LB;
  const float* X = x1 + (size_t)b * LA * EMB;
  float* C = out + (size_t)b * LB * EMB;
  __shared__ float As[16][128];
  __shared__ float Bs[16][128];
  __shared__ float s_m[128], s_iz[128];
  const int tid = threadIdx.x;
  const int tx = tid & 15, ty = tid >> 4;
  const int bm = blockIdx.y * 128;  // j tile
  const int bn = blockIdx.x * 128;  // e tile
  if (tid < 128) {
    s_m[tid]  = g_mcol[b * LB + bm + tid];
    s_iz[tid] = g_izcol[b * LB + bm + tid];
  }
  __syncthreads();
  const int sr = tid >> 4, sc = (tid & 15) << 2;  // direct loader (S row = i = k)
  float cm[8], ciz[8];
#pragma unroll
  for (int c = 0; c < 4; c++) {
    cm[c] = s_m[sc + c];       ciz[c] = s_iz[sc + c];
    cm[c + 4] = s_m[sc + 64 + c]; ciz[c + 4] = s_iz[sc + 64 + c];
  }
  float acc[8][8] = {};
  for (int k0 = 0; k0 < LA; k0 += 16) {
    const float* Sr = S + (size_t)(k0 + sr) * LB + bm;
    float4 v0 = *(const float4*)(Sr + sc);
    float4 v1 = *(const float4*)(Sr + sc + 64);
    float4 w0, w1;
    w0.x = __expf(v0.x - cm[0]) * ciz[0];
    w0.y = __expf(v0.y - cm[1]) * ciz[1];
    w0.z = __expf(v0.z - cm[2]) * ciz[2];
    w0.w = __expf(v0.w - cm[3]) * ciz[3];
    w1.x = __expf(v1.x - cm[4]) * ciz[4];
    w1.y = __expf(v1.y - cm[5]) * ciz[5];
    w1.z = __expf(v1.z - cm[6]) * ciz[6];
    w1.w = __expf(v1.w - cm[7]) * ciz[7];
    *(float4*)&As[sr][sc]      = w0;
    *(float4*)&As[sr][sc + 64] = w1;
    const float* Xr = X + (size_t)(k0 + sr) * EMB + bn;
    *(float4*)&Bs[sr][sc]      = *(const float4*)(Xr + sc);
    *(float4*)&Bs[sr][sc + 64] = *(const float4*)(Xr + sc + 64);
    __syncthreads();
    INNER_LOOP();
    __syncthreads();
  }
#pragma unroll
  for (int i = 0; i < 8; i++) {
    float* Cr = C + (size_t)(bm + ty * 8 + i) * EMB + bn + tx * 8;
    *(float4*)(Cr + 0) = *(float4*)&acc[i][0];
    *(float4*)(Cr + 4) = *(float4*)&acc[i][4];
  }
}

// ---------------- launch -----------------------------------------------------
extern "C" void kernel_launch(void* const* d_in, const int* in_sizes, int n_in,
                              void* d_out, int out_size) {
  const float* x1 = (const float*)d_in[0];
  const float* x2 = (const float*)d_in[1];
  const float* W1 = (const float*)d_in[2];
  const float* b1 = (const float*)d_in[3];
  const float* W2 = (const float*)d_in[4];
  const float* b2 = (const float*)d_in[5];
  const float* W3 = (const float*)d_in[6];
  const float* b3 = (const float*)d_in[7];
  float* out = (float*)d_out;
  float* alpha_out = out;                                   // [B, LB, EMB]
  float* beta_out  = out + (size_t)BATCH * LB * EMB;        // [B, LA, EMB]

  float *t1, *t2, *fa, *fb;
  cudaGetSymbolAddress((void**)&t1, g_t1);
  cudaGetSymbolAddress((void**)&t2, g_t2);
  cudaGetSymbolAddress((void**)&fa, g_fa);
  cudaGetSymbolAddress((void**)&fb, g_fb);

  dim3 blk(256);
  dim3 gMLP(HID / 128, MTOT / 128);  // (8, 64)

  // MLP for x1 -> fa
  gemm_bias_relu<<<gMLP, blk>>>(x1, W1, b1, t1, MTOT, HID, EMB);
  gemm_bias_relu<<<gMLP, blk>>>(t1, W2, b2, t2, MTOT, HID, HID);
  gemm_bias_relu<<<gMLP, blk>>>(t2, W3, b3, fa, MTOT, HID, HID);
  // MLP for x2 -> fb
  gemm_bias_relu<<<gMLP, blk>>>(x2, W1, b1, t1, MTOT, HID, EMB);
  gemm_bias_relu<<<gMLP, blk>>>(t1, W2, b2, t2, MTOT, HID, HID);
  gemm_bias_relu<<<gMLP, blk>>>(t2, W3, b3, fb, MTOT, HID, HID);

  // scores
  scores_gemm<<<dim3(LB / 128, LA / 128, BATCH), blk>>>();

  // softmax stats
  row_stats_kernel<<<BATCH * LA, 256>>>();
  col_stats_kernel<<<dim3(LB / 128, BATCH), dim3(128, 8)>>>();

  // attention outputs
  beta_gemm<<<dim3(EMB / 128, LA / 128, BATCH), blk>>>(x2, beta_out);
  alpha_gemm<<<dim3(EMB / 128, LB / 128, BATCH), blk>>>(x1, alpha_out);
}

// round 3
// speedup vs baseline: 1.7362x; 1.7362x over previous
#include <cuda_runtime.h>
#include <cuda_bf16.h>
#include <stdint.h>
#include <math.h>

#define BATCH 2
#define LA 4096
#define LB 4096
#define EMB 1024
#define HID 1024
#define MTOT (BATCH * LA)

typedef __nv_bfloat16 bf16;

// ---------------- scratch (device globals: no alloc allowed) ----------------
__device__ bf16 g_x1h[(size_t)MTOT * EMB], g_x1l[(size_t)MTOT * EMB];
__device__ bf16 g_x2h[(size_t)MTOT * EMB], g_x2l[(size_t)MTOT * EMB];
__device__ bf16 g_w1h[(size_t)HID * EMB], g_w1l[(size_t)HID * EMB];
__device__ bf16 g_w2h[(size_t)HID * HID], g_w2l[(size_t)HID * HID];
__device__ bf16 g_w3h[(size_t)HID * HID], g_w3l[(size_t)HID * HID];
__device__ bf16 g_t1h[(size_t)MTOT * HID], g_t1l[(size_t)MTOT * HID];
__device__ bf16 g_t2h[(size_t)MTOT * HID], g_t2l[(size_t)MTOT * HID];
__device__ bf16 g_fah[(size_t)MTOT * HID], g_fal[(size_t)MTOT * HID];
__device__ bf16 g_fbh[(size_t)MTOT * HID], g_fbl[(size_t)MTOT * HID];
__device__ bf16 g_x1th[(size_t)BATCH * EMB * LA], g_x1tl[(size_t)BATCH * EMB * LA];
__device__ bf16 g_x2th[(size_t)BATCH * EMB * LB], g_x2tl[(size_t)BATCH * EMB * LB];
__device__ float g_S[(size_t)BATCH * LA * LB];
__device__ bf16 g_prh[(size_t)BATCH * LA * LB], g_prl[(size_t)BATCH * LA * LB];
__device__ bf16 g_pch[(size_t)BATCH * LB * LA], g_pcl[(size_t)BATCH * LB * LA];
__device__ float g_mrow[BATCH * LA], g_izrow[BATCH * LA];
__device__ float g_mcol[BATCH * LB], g_izcol[BATCH * LB];

// ---------------- ptx helpers ------------------------------------------------
__device__ __forceinline__ uint32_t smem_u32(const void* p) {
  uint32_t a;
  asm("{ .reg .u64 t; cvta.to.shared.u64 t, %1; cvt.u32.u64 %0, t; }"
      : "=r"(a) : "l"(p));
  return a;
}
__device__ __forceinline__ void cp16(uint32_t d, const void* s) {
  asm volatile("cp.async.cg.shared.global [%0], [%1], 16;" :: "r"(d), "l"(s));
}
__device__ __forceinline__ void cp_commit() {
  asm volatile("cp.async.commit_group;");
}
template <int N>
__device__ __forceinline__ void cp_wait() {
  asm volatile("cp.async.wait_group %0;" :: "n"(N));
}
__device__ __forceinline__ void ldsm4(uint32_t* r, uint32_t a) {
  asm volatile("ldmatrix.sync.aligned.m8n8.x4.shared.b16 {%0,%1,%2,%3}, [%4];"
               : "=r"(r[0]), "=r"(r[1]), "=r"(r[2]), "=r"(r[3]) : "r"(a));
}
__device__ __forceinline__ void mma16816(float* d, const uint32_t* a, const uint32_t* b) {
  asm volatile(
      "mma.sync.aligned.m16n8k16.row.col.f32.bf16.bf16.f32 "
      "{%0,%1,%2,%3}, {%4,%5,%6,%7}, {%8,%9}, {%0,%1,%2,%3};"
      : "+f"(d[0]), "+f"(d[1]), "+f"(d[2]), "+f"(d[3])
      : "r"(a[0]), "r"(a[1]), "r"(a[2]), "r"(a[3]), "r"(b[0]), "r"(b[1]));
}

__device__ __forceinline__ void split_store(bf16* oh, bf16* ol, size_t o, float v) {
  bf16 h = __float2bfloat16(v);
  oh[o] = h;
  ol[o] = __float2bfloat16(v - __bfloat162float(h));
}
__device__ __forceinline__ void split2_store(bf16* oh, bf16* ol, size_t o,
                                             float v0, float v1) {
  bf16 h0 = __float2bfloat16(v0), h1 = __float2bfloat16(v1);
  __nv_bfloat162 hp; hp.x = h0; hp.y = h1;
  __nv_bfloat162 lp;
  lp.x = __float2bfloat16(v0 - __bfloat162float(h0));
  lp.y = __float2bfloat16(v1 - __bfloat162float(h1));
  *(__nv_bfloat162*)(oh + o) = hp;
  *(__nv_bfloat162*)(ol + o) = lp;
}

// ---------------- mma.sync GEMM: C[128x128] = A[M,K] @ B[N,K]^T --------------
// A,B as bf16 (hi,lo) pairs, K-major. 3-pass split: AhBh + AhBl + AlBh.
// EPI 0: fp32 C.  EPI 1: bias+relu -> bf16 hi/lo pair.
static constexpr int LDM = 80;               // smem bytes per 32-bf16 row (padded)
static constexpr int TILE_B = 128 * LDM;     // 10240
static constexpr int STAGE = 4 * TILE_B;     // Ah,Al,Bh,Bl
static constexpr int SMEM_DYN = 2 * STAGE;   // 81920

template <int EPI>
__global__ void __launch_bounds__(256) gemm_mma(
    const bf16* __restrict__ Ah, const bf16* __restrict__ Al,
    const bf16* __restrict__ Bh, const bf16* __restrict__ Bl,
    int K, long long sA, long long sB,
    float* __restrict__ C, bf16* __restrict__ Oh, bf16* __restrict__ Ol,
    const float* __restrict__ bias, long long sC, int ldc) {
  extern __shared__ char smem[];
  const uint32_t sb = smem_u32(smem);
  const int tid = threadIdx.x;
  const int lane = tid & 31;
  const int wm = (tid >> 5) >> 2;   // 0..1
  const int wn = (tid >> 5) & 3;    // 0..3
  const int b = blockIdx.z;
  const size_t bm = (size_t)blockIdx.y * 128, bn = (size_t)blockIdx.x * 128;

  // -------- loader mapping: 4 tiles x 64 threads, 2 rows x 4 chunks each ----
  const int ltile = tid >> 6;
  const int lr = (tid & 63) * 2;
  const bf16* lp;
  if (ltile == 0)      lp = Ah + (size_t)b * sA + (bm + lr) * (size_t)K;
  else if (ltile == 1) lp = Al + (size_t)b * sA + (bm + lr) * (size_t)K;
  else if (ltile == 2) lp = Bh + (size_t)b * sB + (bn + lr) * (size_t)K;
  else                 lp = Bl + (size_t)b * sB + (bn + lr) * (size_t)K;
  const uint32_t ldst = sb + (uint32_t)(ltile * TILE_B + lr * LDM);

#define LOADST(c, s)                                                          \
  do {                                                                        \
    const bf16* src_ = lp + (size_t)(c) * 32;                                 \
    uint32_t d_ = ldst + (uint32_t)(s) * STAGE;                               \
    _Pragma("unroll") for (int rr_ = 0; rr_ < 2; rr_++)                       \
      _Pragma("unroll") for (int ch_ = 0; ch_ < 4; ch_++)                     \
        cp16(d_ + rr_ * LDM + ch_ * 16, src_ + (size_t)rr_ * K + ch_ * 8);    \
    cp_commit();                                                              \
  } while (0)

  // -------- fragment smem addresses (stage 0, kstep 0) ----------------------
  uint32_t aAh[4], aAl[4], aBh[2], aBl[2];
#pragma unroll
  for (int i = 0; i < 4; i++) {
    int row = wm * 64 + i * 16 + (lane & 15);
    uint32_t off = (uint32_t)(row * LDM + (lane >> 4) * 16);
    aAh[i] = sb + off;
    aAl[i] = sb + TILE_B + off;
  }
#pragma unroll
  for (int j = 0; j < 2; j++) {
    int row = wn * 32 + j * 16 + (lane & 7) + ((lane >> 4) & 1) * 8;
    uint32_t off = (uint32_t)(row * LDM + ((lane >> 3) & 1) * 16);
    aBh[j] = sb + 2 * TILE_B + off;
    aBl[j] = sb + 3 * TILE_B + off;
  }

  float acc[4][4][4];
#pragma unroll
  for (int i = 0; i < 4; i++)
#pragma unroll
    for (int j = 0; j < 4; j++)
#pragma unroll
      for (int r = 0; r < 4; r++) acc[i][j][r] = 0.f;

  const int NC = K >> 5;
  LOADST(0, 0);
  for (int c = 0; c < NC; c++) {
    const int s = c & 1;
    if (c + 1 < NC) { LOADST(c + 1, s ^ 1); cp_wait<1>(); }
    else            { cp_wait<0>(); }
    __syncthreads();
#pragma unroll
    for (int ks = 0; ks < 2; ks++) {
      const uint32_t soff = (uint32_t)s * STAGE + ks * 32;
      uint32_t fAh[4][4], fAl[4][4], fBh[2][4], fBl[2][4];
#pragma unroll
      for (int i = 0; i < 4; i++) {
        ldsm4(fAh[i], aAh[i] + soff);
        ldsm4(fAl[i], aAl[i] + soff);
      }
#pragma unroll
      for (int j = 0; j < 2; j++) {
        ldsm4(fBh[j], aBh[j] + soff);
        ldsm4(fBl[j], aBl[j] + soff);
      }
#pragma unroll
      for (int i = 0; i < 4; i++)
#pragma unroll
        for (int j = 0; j < 2; j++)
#pragma unroll
          for (int h = 0; h < 2; h++) {
            float* d = acc[i][j * 2 + h];
            mma16816(d, fAh[i], &fBh[j][h * 2]);
            mma16816(d, fAh[i], &fBl[j][h * 2]);
            mma16816(d, fAl[i], &fBh[j][h * 2]);
          }
    }
    __syncthreads();
  }

  // -------- epilogue: direct global stores ----------------------------------
  const int l4 = lane >> 2, l2 = (lane & 3) * 2;
#pragma unroll
  for (int i = 0; i < 4; i++) {
#pragma unroll
    for (int j = 0; j < 4; j++) {
      const size_t row = bm + wm * 64 + i * 16 + l4;
      const size_t col = bn + wn * 32 + j * 8 + l2;
      float* a = acc[i][j];
      const size_t o = (size_t)b * sC + row * (size_t)ldc + col;
      if (EPI == 0) {
        float2 v0; v0.x = a[0]; v0.y = a[1];
        float2 v1; v1.x = a[2]; v1.y = a[3];
        *(float2*)(C + o) = v0;
        *(float2*)(C + o + 8 * (size_t)ldc) = v1;
      } else {
        float2 bv = *(const float2*)(bias + col);
        split2_store(Oh, Ol, o, fmaxf(a[0] + bv.x, 0.f), fmaxf(a[1] + bv.y, 0.f));
        split2_store(Oh, Ol, o + 8 * (size_t)ldc,
                     fmaxf(a[2] + bv.x, 0.f), fmaxf(a[3] + bv.y, 0.f));
      }
    }
  }
}

// ---------------- conversion kernels -----------------------------------------
__global__ void k_split(const float* __restrict__ x, bf16* __restrict__ oh,
                        bf16* __restrict__ ol, size_t n) {
  size_t i = (size_t)blockIdx.x * blockDim.x + threadIdx.x;
  if (i < n) split_store(oh, ol, i, x[i]);
}

__global__ void k_tsplit(const float* __restrict__ in, bf16* __restrict__ oh,
                         bf16* __restrict__ ol, int R, int Cc,
                         long long sIn, long long sOut) {
  __shared__ float t[32][33];
  const int b = blockIdx.z;
  const int r0 = blockIdx.y * 32, c0 = blockIdx.x * 32;
  const int tx = threadIdx.x, ty = threadIdx.y;
  const float* pin = in + (size_t)b * sIn;
#pragma unroll
  for (int k = 0; k < 4; k++)
    t[ty + 8 * k][tx] = pin[(size_t)(r0 + ty + 8 * k) * Cc + c0 + tx];
  __syncthreads();
#pragma unroll
  for (int k = 0; k < 4; k++) {
    float v = t[tx][ty + 8 * k];
    size_t o = (size_t)b * sOut + (size_t)(c0 + ty + 8 * k) * R + r0 + tx;
    split_store(oh, ol, o, v);
  }
}

__global__ void k_prow() {
  const int row = blockIdx.y;
  const int j = blockIdx.x * 256 + threadIdx.x;
  const float m = g_mrow[row], iz = g_izrow[row];
  const size_t o = (size_t)row * LB + j;
  float p = __expf(g_S[o] - m) * iz;
  split_store(g_prh, g_prl, o, p);
}

__global__ void k_pcolT() {
  __shared__ float t[32][33];
  const int b = blockIdx.z;
  const int i0 = blockIdx.y * 32, j0 = blockIdx.x * 32;
  const int tx = threadIdx.x, ty = threadIdx.y;
  const float* S = g_S + (size_t)b * LA * LB;
#pragma unroll
  for (int k = 0; k < 4; k++)
    t[ty + 8 * k][tx] = S[(size_t)(i0 + ty + 8 * k) * LB + j0 + tx];
  __syncthreads();
#pragma unroll
  for (int k = 0; k < 4; k++) {
    const int j = j0 + ty + 8 * k;
    float p = __expf(t[tx][ty + 8 * k] - g_mcol[b * LB + j]) * g_izcol[b * LB + j];
    size_t o = (size_t)b * LB * LA + (size_t)j * LA + i0 + tx;
    split_store(g_pch, g_pcl, o, p);
  }
}

// ---------------- softmax stats ----------------------------------------------
__device__ __forceinline__ void olcomb(float& m, float& z, float m2, float z2) {
  if (m2 > m) { z = z * __expf(m - m2) + z2; m = m2; }
  else        { z = z + z2 * __expf(m2 - m); }
}

__global__ void row_stats_kernel() {
  const int row = blockIdx.x;
  const float* s = g_S + (size_t)row * LB;
  float m = -3.0e38f, z = 0.f;
  for (int j = threadIdx.x; j < LB; j += 256) {
    float v = s[j];
    if (v > m) { z = z * __expf(m - v) + 1.f; m = v; }
    else       { z += __expf(v - m); }
  }
  __shared__ float sm[256], sz[256];
  sm[threadIdx.x] = m; sz[threadIdx.x] = z;
  __syncthreads();
  for (int st = 128; st > 0; st >>= 1) {
    if (threadIdx.x < st) {
      float m1 = sm[threadIdx.x], z1 = sz[threadIdx.x];
      olcomb(m1, z1, sm[threadIdx.x + st], sz[threadIdx.x + st]);
      sm[threadIdx.x] = m1; sz[threadIdx.x] = z1;
    }
    __syncthreads();
  }
  if (threadIdx.x == 0) { g_mrow[row] = sm[0]; g_izrow[row] = 1.f / sz[0]; }
}

__global__ void col_stats_kernel() {
  const int b = blockIdx.y;
  const int col = blockIdx.x * 128 + threadIdx.x;
  const float* s = g_S + (size_t)b * LA * LB + col;
  float m = -3.0e38f, z = 0.f;
  for (int i = threadIdx.y; i < LA; i += 8) {
    float v = s[(size_t)i * LB];
    if (v > m) { z = z * __expf(m - v) + 1.f; m = v; }
    else       { z += __expf(v - m); }
  }
  __shared__ float sm[8][128], sz[8][128];
  sm[threadIdx.y][threadIdx.x] = m; sz[threadIdx.y][threadIdx.x] = z;
  __syncthreads();
  if (threadIdx.y == 0) {
#pragma unroll
    for (int y = 1; y < 8; y++) olcomb(m, z, sm[y][threadIdx.x], sz[y][threadIdx.x]);
    g_mcol[b * LB + col] = m;
    g_izcol[b * LB + col] = 1.f / z;
  }
}

// ---------------- launch -----------------------------------------------------
#define GSA(T, v, sym) T* v; cudaGetSymbolAddress((void**)&v, sym)

extern "C" void kernel_launch(void* const* d_in, const int* in_sizes, int n_in,
                              void* d_out, int out_size) {
  const float* x1 = (const float*)d_in[0];
  const float* x2 = (const float*)d_in[1];
  const float* W1 = (const float*)d_in[2];
  const float* b1 = (const float*)d_in[3];
  const float* W2 = (const float*)d_in[4];
  const float* b2 = (const float*)d_in[5];
  const float* W3 = (const float*)d_in[6];
  const float* b3 = (const float*)d_in[7];
  float* out = (float*)d_out;
  float* alpha_out = out;                             // [B, LB, EMB]
  float* beta_out = out + (size_t)BATCH * LB * EMB;   // [B, LA, EMB]

  GSA(bf16, x1h, g_x1h); GSA(bf16, x1l, g_x1l);
  GSA(bf16, x2h, g_x2h); GSA(bf16, x2l, g_x2l);
  GSA(bf16, w1h, g_w1h); GSA(bf16, w1l, g_w1l);
  GSA(bf16, w2h, g_w2h); GSA(bf16, w2l, g_w2l);
  GSA(bf16, w3h, g_w3h); GSA(bf16, w3l, g_w3l);
  GSA(bf16, t1h, g_t1h); GSA(bf16, t1l, g_t1l);
  GSA(bf16, t2h, g_t2h); GSA(bf16, t2l, g_t2l);
  GSA(bf16, fah, g_fah); GSA(bf16, fal, g_fal);
  GSA(bf16, fbh, g_fbh); GSA(bf16, fbl, g_fbl);
  GSA(bf16, x1th, g_x1th); GSA(bf16, x1tl, g_x1tl);
  GSA(bf16, x2th, g_x2th); GSA(bf16, x2tl, g_x2tl);
  GSA(bf16, prh, g_prh); GSA(bf16, prl, g_prl);
  GSA(bf16, pch, g_pch); GSA(bf16, pcl, g_pcl);
  GSA(float, S, g_S);

  cudaFuncSetAttribute(gemm_mma<0>, cudaFuncAttributeMaxDynamicSharedMemorySize, SMEM_DYN);
  cudaFuncSetAttribute(gemm_mma<1>, cudaFuncAttributeMaxDynamicSharedMemorySize, SMEM_DYN);

  const size_t nx = (size_t)MTOT * EMB;
  dim3 t8(32, 8);

  // input conversions
  k_split<<<(unsigned)((nx + 255) / 256), 256>>>(x1, x1h, x1l, nx);
  k_split<<<(unsigned)((nx + 255) / 256), 256>>>(x2, x2h, x2l, nx);
  k_tsplit<<<dim3(HID / 32, EMB / 32, 1), t8>>>(W1, w1h, w1l, EMB, HID, 0, 0);
  k_tsplit<<<dim3(HID / 32, HID / 32, 1), t8>>>(W2, w2h, w2l, HID, HID, 0, 0);
  k_tsplit<<<dim3(HID / 32, HID / 32, 1), t8>>>(W3, w3h, w3l, HID, HID, 0, 0);
  k_tsplit<<<dim3(EMB / 32, LA / 32, BATCH), t8>>>(x1, x1th, x1tl, LA, EMB,
                                                   (long long)LA * EMB, (long long)EMB * LA);
  k_tsplit<<<dim3(EMB / 32, LB / 32, BATCH), t8>>>(x2, x2th, x2tl, LB, EMB,
                                                   (long long)LB * EMB, (long long)EMB * LB);

  dim3 gMLP(HID / 128, MTOT / 128, 1);
  // MLP x1 -> fa
  gemm_mma<1><<<gMLP, 256, SMEM_DYN>>>(x1h, x1l, w1h, w1l, EMB, 0, 0, nullptr, t1h, t1l, b1, 0, HID);
  gemm_mma<1><<<gMLP, 256, SMEM_DYN>>>(t1h, t1l, w2h, w2l, HID, 0, 0, nullptr, t2h, t2l, b2, 0, HID);
  gemm_mma<1><<<gMLP, 256, SMEM_DYN>>>(t2h, t2l, w3h, w3l, HID, 0, 0, nullptr, fah, fal, b3, 0, HID);
  // MLP x2 -> fb
  gemm_mma<1><<<gMLP, 256, SMEM_DYN>>>(x2h, x2l, w1h, w1l, EMB, 0, 0, nullptr, t1h, t1l, b1, 0, HID);
  gemm_mma<1><<<gMLP, 256, SMEM_DYN>>>(t1h, t1l, w2h, w2l, HID, 0, 0, nullptr, t2h, t2l, b2, 0, HID);
  gemm_mma<1><<<gMLP, 256, SMEM_DYN>>>(t2h, t2l, w3h, w3l, HID, 0, 0, nullptr, fbh, fbl, b3, 0, HID);

  // scores: S[b] = fa[b] @ fb[b]^T
  gemm_mma<0><<<dim3(LB / 128, LA / 128, BATCH), 256, SMEM_DYN>>>(
      fah, fal, fbh, fbl, HID, (long long)LA * HID, (long long)LB * HID,
      S, nullptr, nullptr, nullptr, (long long)LA * LB, LB);

  // softmax stats + probability conversion
  row_stats_kernel<<<BATCH * LA, 256>>>();
  col_stats_kernel<<<dim3(LB / 128, BATCH), dim3(128, 8)>>>();
  k_prow<<<dim3(LB / 256, BATCH * LA), 256>>>();
  k_pcolT<<<dim3(LB / 32, LA / 32, BATCH), t8>>>();

  // beta = Prow @ x2   (B operand = x2^T pairs)
  gemm_mma<0><<<dim3(EMB / 128, LA / 128, BATCH), 256, SMEM_DYN>>>(
      prh, prl, x2th, x2tl, LB, (long long)LA * LB, (long long)EMB * LB,
      beta_out, nullptr, nullptr, nullptr, (long long)LA * EMB, EMB);
  // alpha = PcolT @ x1 (B operand = x1^T pairs)
  gemm_mma<0><<<dim3(EMB / 128, LB / 128, BATCH), 256, SMEM_DYN>>>(
      pch, pcl, x1th, x1tl, LA, (long long)LB * LA, (long long)EMB * LA,
      alpha_out, nullptr, nullptr, nullptr, (long long)LB * EMB, EMB);
}

// round 4
// speedup vs baseline: 1.7402x; 1.0023x over previous
#include <cuda_runtime.h>
#include <cuda_bf16.h>
#include <stdint.h>
#include <math.h>

#define BATCH 2
#define LA 4096
#define LB 4096
#define EMB 1024
#define HID 1024
#define MTOT (BATCH * LA)

typedef __nv_bfloat16 bf16;

// ---------------- scratch (device globals: no alloc allowed) ----------------
__device__ bf16 g_x1h[(size_t)MTOT * EMB], g_x1l[(size_t)MTOT * EMB];
__device__ bf16 g_x2h[(size_t)MTOT * EMB], g_x2l[(size_t)MTOT * EMB];
__device__ bf16 g_w1h[(size_t)HID * EMB], g_w1l[(size_t)HID * EMB];
__device__ bf16 g_w2h[(size_t)HID * HID], g_w2l[(size_t)HID * HID];
__device__ bf16 g_w3h[(size_t)HID * HID], g_w3l[(size_t)HID * HID];
__device__ bf16 g_t1h[(size_t)MTOT * HID], g_t1l[(size_t)MTOT * HID];
__device__ bf16 g_t2h[(size_t)MTOT * HID], g_t2l[(size_t)MTOT * HID];
__device__ bf16 g_fah[(size_t)MTOT * HID], g_fal[(size_t)MTOT * HID];
__device__ bf16 g_fbh[(size_t)MTOT * HID], g_fbl[(size_t)MTOT * HID];
__device__ bf16 g_x1th[(size_t)BATCH * EMB * LA], g_x1tl[(size_t)BATCH * EMB * LA];
__device__ bf16 g_x2th[(size_t)BATCH * EMB * LB], g_x2tl[(size_t)BATCH * EMB * LB];
__device__ float g_S[(size_t)BATCH * LA * LB];
__device__ bf16 g_prh[(size_t)BATCH * LA * LB], g_prl[(size_t)BATCH * LA * LB];
__device__ bf16 g_pch[(size_t)BATCH * LB * LA], g_pcl[(size_t)BATCH * LB * LA];
__device__ float g_mrow[BATCH * LA], g_izrow[BATCH * LA];
__device__ float g_mcol[BATCH * LB], g_izcol[BATCH * LB];

// ---------------- ptx helpers ------------------------------------------------
__device__ __forceinline__ uint32_t smem_u32(const void* p) {
  uint32_t a;
  asm("{ .reg .u64 t; cvta.to.shared.u64 t, %1; cvt.u32.u64 %0, t; }"
      : "=r"(a) : "l"(p));
  return a;
}
__device__ __forceinline__ void cp16(uint32_t d, const void* s) {
  asm volatile("cp.async.cg.shared.global [%0], [%1], 16;" :: "r"(d), "l"(s));
}
__device__ __forceinline__ void cp_commit() {
  asm volatile("cp.async.commit_group;");
}
template <int N>
__device__ __forceinline__ void cp_wait() {
  asm volatile("cp.async.wait_group %0;" :: "n"(N));
}
__device__ __forceinline__ void ldsm4(uint32_t* r, uint32_t a) {
  asm volatile("ldmatrix.sync.aligned.m8n8.x4.shared.b16 {%0,%1,%2,%3}, [%4];"
               : "=r"(r[0]), "=r"(r[1]), "=r"(r[2]), "=r"(r[3]) : "r"(a));
}
__device__ __forceinline__ void mma16816(float* d, const uint32_t* a, const uint32_t* b) {
  asm volatile(
      "mma.sync.aligned.m16n8k16.row.col.f32.bf16.bf16.f32 "
      "{%0,%1,%2,%3}, {%4,%5,%6,%7}, {%8,%9}, {%0,%1,%2,%3};"
      : "+f"(d[0]), "+f"(d[1]), "+f"(d[2]), "+f"(d[3])
      : "r"(a[0]), "r"(a[1]), "r"(a[2]), "r"(a[3]), "r"(b[0]), "r"(b[1]));
}

__device__ __forceinline__ void split_store(bf16* oh, bf16* ol, size_t o, float v) {
  bf16 h = __float2bfloat16(v);
  oh[o] = h;
  ol[o] = __float2bfloat16(v - __bfloat162float(h));
}
__device__ __forceinline__ void split2_store(bf16* oh, bf16* ol, size_t o,
                                             float v0, float v1) {
  bf16 h0 = __float2bfloat16(v0), h1 = __float2bfloat16(v1);
  __nv_bfloat162 hp; hp.x = h0; hp.y = h1;
  __nv_bfloat162 lp;
  lp.x = __float2bfloat16(v0 - __bfloat162float(h0));
  lp.y = __float2bfloat16(v1 - __bfloat162float(h1));
  *(__nv_bfloat162*)(oh + o) = hp;
  *(__nv_bfloat162*)(ol + o) = lp;
}

// ---------------- mma.sync GEMM: C[128x128] = A[M,K] @ B[N,K]^T --------------
// A,B as bf16 (hi,lo) pairs, K-major. 3-pass split: AhBh + AhBl + AlBh.
// EPI 0: fp32 C.  EPI 1: bias+relu -> bf16 hi/lo pair.
static constexpr int LDM = 80;               // smem bytes per 32-bf16 row (padded)
static constexpr int TILE_B = 128 * LDM;     // 10240
static constexpr int STAGE = 4 * TILE_B;     // Ah,Al,Bh,Bl
static constexpr int SMEM_DYN = 2 * STAGE;   // 81920

template <int EPI>
__global__ void __launch_bounds__(256) gemm_mma(
    const bf16* __restrict__ Ah, const bf16* __restrict__ Al,
    const bf16* __restrict__ Bh, const bf16* __restrict__ Bl,
    int K, long long sA, long long sB,
    float* __restrict__ C, bf16* __restrict__ Oh, bf16* __restrict__ Ol,
    const float* __restrict__ bias, long long sC, int ldc) {
  extern __shared__ char smem[];
  const uint32_t sb = smem_u32(smem);
  const int tid = threadIdx.x;
  const int lane = tid & 31;
  const int wm = (tid >> 5) >> 2;   // 0..1
  const int wn = (tid >> 5) & 3;    // 0..3
  const int b = blockIdx.z;
  const size_t bm = (size_t)blockIdx.y * 128, bn = (size_t)blockIdx.x * 128;

  // -------- loader mapping: 4 tiles x 64 threads, 2 rows x 4 chunks each ----
  const int ltile = tid >> 6;
  const int lr = (tid & 63) * 2;
  const bf16* lp;
  if (ltile == 0)      lp = Ah + (size_t)b * sA + (bm + lr) * (size_t)K;
  else if (ltile == 1) lp = Al + (size_t)b * sA + (bm + lr) * (size_t)K;
  else if (ltile == 2) lp = Bh + (size_t)b * sB + (bn + lr) * (size_t)K;
  else                 lp = Bl + (size_t)b * sB + (bn + lr) * (size_t)K;
  const uint32_t ldst = sb + (uint32_t)(ltile * TILE_B + lr * LDM);

#define LOADST(c, s)                                                          \
  do {                                                                        \
    const bf16* src_ = lp + (size_t)(c) * 32;                                 \
    uint32_t d_ = ldst + (uint32_t)(s) * STAGE;                               \
    _Pragma("unroll") for (int rr_ = 0; rr_ < 2; rr_++)                       \
      _Pragma("unroll") for (int ch_ = 0; ch_ < 4; ch_++)                     \
        cp16(d_ + rr_ * LDM + ch_ * 16, src_ + (size_t)rr_ * K + ch_ * 8);    \
    cp_commit();                                                              \
  } while (0)

  // -------- fragment smem addresses (stage 0, kstep 0) ----------------------
  uint32_t aAh[4], aAl[4], aBh[2], aBl[2];
#pragma unroll
  for (int i = 0; i < 4; i++) {
    int row = wm * 64 + i * 16 + (lane & 15);
    uint32_t off = (uint32_t)(row * LDM + (lane >> 4) * 16);
    aAh[i] = sb + off;
    aAl[i] = sb + TILE_B + off;
  }
#pragma unroll
  for (int j = 0; j < 2; j++) {
    int row = wn * 32 + j * 16 + (lane & 7) + ((lane >> 4) & 1) * 8;
    uint32_t off = (uint32_t)(row * LDM + ((lane >> 3) & 1) * 16);
    aBh[j] = sb + 2 * TILE_B + off;
    aBl[j] = sb + 3 * TILE_B + off;
  }

  float acc[4][4][4];
#pragma unroll
  for (int i = 0; i < 4; i++)
#pragma unroll
    for (int j = 0; j < 4; j++)
#pragma unroll
      for (int r = 0; r < 4; r++) acc[i][j][r] = 0.f;

  const int NC = K >> 5;
  LOADST(0, 0);
  for (int c = 0; c < NC; c++) {
    const int s = c & 1;
    if (c + 1 < NC) { LOADST(c + 1, s ^ 1); cp_wait<1>(); }
    else            { cp_wait<0>(); }
    __syncthreads();
#pragma unroll
    for (int ks = 0; ks < 2; ks++) {
      const uint32_t soff = (uint32_t)s * STAGE + ks * 32;
      uint32_t fAh[4][4], fAl[4][4], fBh[2][4], fBl[2][4];
#pragma unroll
      for (int i = 0; i < 4; i++) {
        ldsm4(fAh[i], aAh[i] + soff);
        ldsm4(fAl[i], aAl[i] + soff);
      }
#pragma unroll
      for (int j = 0; j < 2; j++) {
        ldsm4(fBh[j], aBh[j] + soff);
        ldsm4(fBl[j], aBl[j] + soff);
      }
#pragma unroll
      for (int i = 0; i < 4; i++)
#pragma unroll
        for (int j = 0; j < 2; j++)
#pragma unroll
          for (int h = 0; h < 2; h++) {
            float* d = acc[i][j * 2 + h];
            mma16816(d, fAh[i], &fBh[j][h * 2]);
            mma16816(d, fAh[i], &fBl[j][h * 2]);
            mma16816(d, fAl[i], &fBh[j][h * 2]);
          }
    }
    __syncthreads();
  }

  // -------- epilogue: direct global stores ----------------------------------
  const int l4 = lane >> 2, l2 = (lane & 3) * 2;
#pragma unroll
  for (int i = 0; i < 4; i++) {
#pragma unroll
    for (int j = 0; j < 4; j++) {
      const size_t row = bm + wm * 64 + i * 16 + l4;
      const size_t col = bn + wn * 32 + j * 8 + l2;
      float* a = acc[i][j];
      const size_t o = (size_t)b * sC + row * (size_t)ldc + col;
      if (EPI == 0) {
        float2 v0; v0.x = a[0]; v0.y = a[1];
        float2 v1; v1.x = a[2]; v1.y = a[3];
        *(float2*)(C + o) = v0;
        *(float2*)(C + o + 8 * (size_t)ldc) = v1;
      } else {
        float2 bv = *(const float2*)(bias + col);
        split2_store(Oh, Ol, o, fmaxf(a[0] + bv.x, 0.f), fmaxf(a[1] + bv.y, 0.f));
        split2_store(Oh, Ol, o + 8 * (size_t)ldc,
                     fmaxf(a[2] + bv.x, 0.f), fmaxf(a[3] + bv.y, 0.f));
      }
    }
  }
}

// ---------------- conversion kernels -----------------------------------------
__global__ void k_split(const float* __restrict__ x, bf16* __restrict__ oh,
                        bf16* __restrict__ ol, size_t n) {
  size_t i = (size_t)blockIdx.x * blockDim.x + threadIdx.x;
  if (i < n) split_store(oh, ol, i, x[i]);
}

__global__ void k_tsplit(const float* __restrict__ in, bf16* __restrict__ oh,
                         bf16* __restrict__ ol, int R, int Cc,
                         long long sIn, long long sOut) {
  __shared__ float t[32][33];
  const int b = blockIdx.z;
  const int r0 = blockIdx.y * 32, c0 = blockIdx.x * 32;
  const int tx = threadIdx.x, ty = threadIdx.y;
  const float* pin = in + (size_t)b * sIn;
#pragma unroll
  for (int k = 0; k < 4; k++)
    t[ty + 8 * k][tx] = pin[(size_t)(r0 + ty + 8 * k) * Cc + c0 + tx];
  __syncthreads();
#pragma unroll
  for (int k = 0; k < 4; k++) {
    float v = t[tx][ty + 8 * k];
    size_t o = (size_t)b * sOut + (size_t)(c0 + ty + 8 * k) * R + r0 + tx;
    split_store(oh, ol, o, v);
  }
}

__global__ void k_prow() {
  const int row = blockIdx.y;
  const int j = blockIdx.x * 256 + threadIdx.x;
  const float m = g_mrow[row], iz = g_izrow[row];
  const size_t o = (size_t)row * LB + j;
  float p = __expf(g_S[o] - m) * iz;
  split_store(g_prh, g_prl, o, p);
}

__global__ void k_pcolT() {
  __shared__ float t[32][33];
  const int b = blockIdx.z;
  const int i0 = blockIdx.y * 32, j0 = blockIdx.x * 32;
  const int tx = threadIdx.x, ty = threadIdx.y;
  const float* S = g_S + (size_t)b * LA * LB;
#pragma unroll
  for (int k = 0; k < 4; k++)
    t[ty + 8 * k][tx] = S[(size_t)(i0 + ty + 8 * k) * LB + j0 + tx];
  __syncthreads();
#pragma unroll
  for (int k = 0; k < 4; k++) {
    const int j = j0 + ty + 8 * k;
    float p = __expf(t[tx][ty + 8 * k] - g_mcol[b * LB + j]) * g_izcol[b * LB + j];
    size_t o = (size_t)b * LB * LA + (size_t)j * LA + i0 + tx;
    split_store(g_pch, g_pcl, o, p);
  }
}

// ---------------- softmax stats ----------------------------------------------
__device__ __forceinline__ void olcomb(float& m, float& z, float m2, float z2) {
  if (m2 > m) { z = z * __expf(m - m2) + z2; m = m2; }
  else        { z = z + z2 * __expf(m2 - m); }
}

__global__ void row_stats_kernel() {
  const int row = blockIdx.x;
  const float* s = g_S + (size_t)row * LB;
  float m = -3.0e38f, z = 0.f;
  for (int j = threadIdx.x; j < LB; j += 256) {
    float v = s[j];
    if (v > m) { z = z * __expf(m - v) + 1.f; m = v; }
    else       { z += __expf(v - m); }
  }
  __shared__ float sm[256], sz[256];
  sm[threadIdx.x] = m; sz[threadIdx.x] = z;
  __syncthreads();
  for (int st = 128; st > 0; st >>= 1) {
    if (threadIdx.x < st) {
      float m1 = sm[threadIdx.x], z1 = sz[threadIdx.x];
      olcomb(m1, z1, sm[threadIdx.x + st], sz[threadIdx.x + st]);
      sm[threadIdx.x] = m1; sz[threadIdx.x] = z1;
    }
    __syncthreads();
  }
  if (threadIdx.x == 0) { g_mrow[row] = sm[0]; g_izrow[row] = 1.f / sz[0]; }
}

__global__ void col_stats_kernel() {
  const int b = blockIdx.y;
  const int col = blockIdx.x * 128 + threadIdx.x;
  const float* s = g_S + (size_t)b * LA * LB + col;
  float m = -3.0e38f, z = 0.f;
  for (int i = threadIdx.y; i < LA; i += 8) {
    float v = s[(size_t)i * LB];
    if (v > m) { z = z * __expf(m - v) + 1.f; m = v; }
    else       { z += __expf(v - m); }
  }
  __shared__ float sm[8][128], sz[8][128];
  sm[threadIdx.y][threadIdx.x] = m; sz[threadIdx.y][threadIdx.x] = z;
  __syncthreads();
  if (threadIdx.y == 0) {
#pragma unroll
    for (int y = 1; y < 8; y++) olcomb(m, z, sm[y][threadIdx.x], sz[y][threadIdx.x]);
    g_mcol[b * LB + col] = m;
    g_izcol[b * LB + col] = 1.f / z;
  }
}

// ---------------- launch -----------------------------------------------------
#define GSA(T, v, sym) T* v; cudaGetSymbolAddress((void**)&v, sym)

extern "C" void kernel_launch(void* const* d_in, const int* in_sizes, int n_in,
                              void* d_out, int out_size) {
  const float* x1 = (const float*)d_in[0];
  const float* x2 = (const float*)d_in[1];
  const float* W1 = (const float*)d_in[2];
  const float* b1 = (const float*)d_in[3];
  const float* W2 = (const float*)d_in[4];
  const float* b2 = (const float*)d_in[5];
  const float* W3 = (const float*)d_in[6];
  const float* b3 = (const float*)d_in[7];
  float* out = (float*)d_out;
  float* alpha_out = out;                             // [B, LB, EMB]
  float* beta_out = out + (size_t)BATCH * LB * EMB;   // [B, LA, EMB]

  GSA(bf16, x1h, g_x1h); GSA(bf16, x1l, g_x1l);
  GSA(bf16, x2h, g_x2h); GSA(bf16, x2l, g_x2l);
  GSA(bf16, w1h, g_w1h); GSA(bf16, w1l, g_w1l);
  GSA(bf16, w2h, g_w2h); GSA(bf16, w2l, g_w2l);
  GSA(bf16, w3h, g_w3h); GSA(bf16, w3l, g_w3l);
  GSA(bf16, t1h, g_t1h); GSA(bf16, t1l, g_t1l);
  GSA(bf16, t2h, g_t2h); GSA(bf16, t2l, g_t2l);
  GSA(bf16, fah, g_fah); GSA(bf16, fal, g_fal);
  GSA(bf16, fbh, g_fbh); GSA(bf16, fbl, g_fbl);
  GSA(bf16, x1th, g_x1th); GSA(bf16, x1tl, g_x1tl);
  GSA(bf16, x2th, g_x2th); GSA(bf16, x2tl, g_x2tl);
  GSA(bf16, prh, g_prh); GSA(bf16, prl, g_prl);
  GSA(bf16, pch, g_pch); GSA(bf16, pcl, g_pcl);
  GSA(float, S, g_S);

  cudaFuncSetAttribute(gemm_mma<0>, cudaFuncAttributeMaxDynamicSharedMemorySize, SMEM_DYN);
  cudaFuncSetAttribute(gemm_mma<1>, cudaFuncAttributeMaxDynamicSharedMemorySize, SMEM_DYN);

  const size_t nx = (size_t)MTOT * EMB;
  dim3 t8(32, 8);

  // input conversions
  k_split<<<(unsigned)((nx + 255) / 256), 256>>>(x1, x1h, x1l, nx);
  k_split<<<(unsigned)((nx + 255) / 256), 256>>>(x2, x2h, x2l, nx);
  k_tsplit<<<dim3(HID / 32, EMB / 32, 1), t8>>>(W1, w1h, w1l, EMB, HID, 0, 0);
  k_tsplit<<<dim3(HID / 32, HID / 32, 1), t8>>>(W2, w2h, w2l, HID, HID, 0, 0);
  k_tsplit<<<dim3(HID / 32, HID / 32, 1), t8>>>(W3, w3h, w3l, HID, HID, 0, 0);
  k_tsplit<<<dim3(EMB / 32, LA / 32, BATCH), t8>>>(x1, x1th, x1tl, LA, EMB,
                                                   (long long)LA * EMB, (long long)EMB * LA);
  k_tsplit<<<dim3(EMB / 32, LB / 32, BATCH), t8>>>(x2, x2th, x2tl, LB, EMB,
                                                   (long long)LB * EMB, (long long)EMB * LB);

  dim3 gMLP(HID / 128, MTOT / 128, 1);
  // MLP x1 -> fa
  gemm_mma<1><<<gMLP, 256, SMEM_DYN>>>(x1h, x1l, w1h, w1l, EMB, 0, 0, nullptr, t1h, t1l, b1, 0, HID);
  gemm_mma<1><<<gMLP, 256, SMEM_DYN>>>(t1h, t1l, w2h, w2l, HID, 0, 0, nullptr, t2h, t2l, b2, 0, HID);
  gemm_mma<1><<<gMLP, 256, SMEM_DYN>>>(t2h, t2l, w3h, w3l, HID, 0, 0, nullptr, fah, fal, b3, 0, HID);
  // MLP x2 -> fb
  gemm_mma<1><<<gMLP, 256, SMEM_DYN>>>(x2h, x2l, w1h, w1l, EMB, 0, 0, nullptr, t1h, t1l, b1, 0, HID);
  gemm_mma<1><<<gMLP, 256, SMEM_DYN>>>(t1h, t1l, w2h, w2l, HID, 0, 0, nullptr, t2h, t2l, b2, 0, HID);
  gemm_mma<1><<<gMLP, 256, SMEM_DYN>>>(t2h, t2l, w3h, w3l, HID, 0, 0, nullptr, fbh, fbl, b3, 0, HID);

  // scores: S[b] = fa[b] @ fb[b]^T
  gemm_mma<0><<<dim3(LB / 128, LA / 128, BATCH), 256, SMEM_DYN>>>(
      fah, fal, fbh, fbl, HID, (long long)LA * HID, (long long)LB * HID,
      S, nullptr, nullptr, nullptr, (long long)LA * LB, LB);

  // softmax stats + probability conversion
  row_stats_kernel<<<BATCH * LA, 256>>>();
  col_stats_kernel<<<dim3(LB / 128, BATCH), dim3(128, 8)>>>();
  k_prow<<<dim3(LB / 256, BATCH * LA), 256>>>();
  k_pcolT<<<dim3(LB / 32, LA / 32, BATCH), t8>>>();

  // beta = Prow @ x2   (B operand = x2^T pairs)
  gemm_mma<0><<<dim3(EMB / 128, LA / 128, BATCH), 256, SMEM_DYN>>>(
      prh, prl, x2th, x2tl, LB, (long long)LA * LB, (long long)EMB * LB,
      beta_out, nullptr, nullptr, nullptr, (long long)LA * EMB, EMB);
  // alpha = PcolT @ x1 (B operand = x1^T pairs)
  gemm_mma<0><<<dim3(EMB / 128, LB / 128, BATCH), 256, SMEM_DYN>>>(
      pch, pcl, x1th, x1tl, LA, (long long)LB * LA, (long long)EMB * LA,
      alpha_out, nullptr, nullptr, nullptr, (long long)LB * EMB, EMB);
}

// round 5
// speedup vs baseline: 1.7760x; 1.0206x over previous
#include <cuda_runtime.h>
#include <cuda_bf16.h>
#include <stdint.h>
#include <math.h>

#define BATCH 2
#define LA 4096
#define LB 4096
#define EMB 1024
#define HID 1024
#define MTOT (BATCH * LA)

typedef __nv_bfloat16 bf16;

// ---------------- scratch (device globals: no alloc allowed) ----------------
__device__ bf16 g_x1h[(size_t)MTOT * EMB], g_x1l[(size_t)MTOT * EMB];
__device__ bf16 g_x2h[(size_t)MTOT * EMB], g_x2l[(size_t)MTOT * EMB];
__device__ bf16 g_w1h[(size_t)HID * EMB], g_w1l[(size_t)HID * EMB];
__device__ bf16 g_w2h[(size_t)HID * HID], g_w2l[(size_t)HID * HID];
__device__ bf16 g_w3h[(size_t)HID * HID], g_w3l[(size_t)HID * HID];
__device__ bf16 g_t1h[(size_t)MTOT * HID], g_t1l[(size_t)MTOT * HID];
__device__ bf16 g_t2h[(size_t)MTOT * HID], g_t2l[(size_t)MTOT * HID];
__device__ bf16 g_fah[(size_t)MTOT * HID], g_fal[(size_t)MTOT * HID];
__device__ bf16 g_fbh[(size_t)MTOT * HID], g_fbl[(size_t)MTOT * HID];
__device__ bf16 g_x1th[(size_t)BATCH * EMB * LA], g_x1tl[(size_t)BATCH * EMB * LA];
__device__ bf16 g_x2th[(size_t)BATCH * EMB * LB], g_x2tl[(size_t)BATCH * EMB * LB];
__device__ float g_S[(size_t)BATCH * LA * LB];
__device__ bf16 g_prh[(size_t)BATCH * LA * LB], g_prl[(size_t)BATCH * LA * LB];
__device__ bf16 g_pch[(size_t)BATCH * LB * LA], g_pcl[(size_t)BATCH * LB * LA];
__device__ float g_mrow[BATCH * LA], g_izrow[BATCH * LA];
__device__ float g_mcol[BATCH * LB], g_izcol[BATCH * LB];

// ---------------- ptx helpers ------------------------------------------------
__device__ __forceinline__ uint32_t smem_u32(const void* p) {
  uint32_t a;
  asm("{ .reg .u64 t; cvta.to.shared.u64 t, %1; cvt.u32.u64 %0, t; }"
      : "=r"(a) : "l"(p));
  return a;
}
__device__ __forceinline__ void cp16(uint32_t d, const void* s) {
  asm volatile("cp.async.cg.shared.global [%0], [%1], 16;" :: "r"(d), "l"(s));
}
__device__ __forceinline__ void cp_commit() {
  asm volatile("cp.async.commit_group;");
}
template <int N>
__device__ __forceinline__ void cp_wait() {
  asm volatile("cp.async.wait_group %0;" :: "n"(N));
}
__device__ __forceinline__ void ldsm4(uint32_t* r, uint32_t a) {
  asm volatile("ldmatrix.sync.aligned.m8n8.x4.shared.b16 {%0,%1,%2,%3}, [%4];"
               : "=r"(r[0]), "=r"(r[1]), "=r"(r[2]), "=r"(r[3]) : "r"(a));
}
__device__ __forceinline__ void mma16816(float* d, const uint32_t* a, const uint32_t* b) {
  asm volatile(
      "mma.sync.aligned.m16n8k16.row.col.f32.bf16.bf16.f32 "
      "{%0,%1,%2,%3}, {%4,%5,%6,%7}, {%8,%9}, {%0,%1,%2,%3};"
      : "+f"(d[0]), "+f"(d[1]), "+f"(d[2]), "+f"(d[3])
      : "r"(a[0]), "r"(a[1]), "r"(a[2]), "r"(a[3]), "r"(b[0]), "r"(b[1]));
}

__device__ __forceinline__ void split_store(bf16* oh, bf16* ol, size_t o, float v) {
  bf16 h = __float2bfloat16(v);
  oh[o] = h;
  ol[o] = __float2bfloat16(v - __bfloat162float(h));
}
__device__ __forceinline__ void split2_store(bf16* oh, bf16* ol, size_t o,
                                             float v0, float v1) {
  bf16 h0 = __float2bfloat16(v0), h1 = __float2bfloat16(v1);
  __nv_bfloat162 hp; hp.x = h0; hp.y = h1;
  __nv_bfloat162 lp;
  lp.x = __float2bfloat16(v0 - __bfloat162float(h0));
  lp.y = __float2bfloat16(v1 - __bfloat162float(h1));
  *(__nv_bfloat162*)(oh + o) = hp;
  *(__nv_bfloat162*)(ol + o) = lp;
}

// ---------------- mma.sync GEMM: C[128x256] = A[M,K] @ B[N,K]^T --------------
// A,B as bf16 (hi,lo) pairs, K-major. 3-pass split: AhBh + AhBl + AlBh.
// CTA 128(M)x256(N), 8 warps = 2(M)x4(N), warp tile 64x64, k-chunk 32.
static constexpr int LDM = 80;                // smem bytes per 32-bf16 row (padded)
static constexpr int TA = 128 * LDM;          // 10240 (one A tile)
static constexpr int TB = 256 * LDM;          // 20480 (one B tile)
static constexpr int STAGE = 2 * TA + 2 * TB; // 61440
static constexpr int SMEM_DYN = 2 * STAGE;    // 122880

template <int EPI>
__global__ void __launch_bounds__(256, 1) gemm_mma(
    const bf16* __restrict__ Ah, const bf16* __restrict__ Al,
    const bf16* __restrict__ Bh, const bf16* __restrict__ Bl,
    int K, long long sA, long long sB,
    float* __restrict__ C, bf16* __restrict__ Oh, bf16* __restrict__ Ol,
    const float* __restrict__ bias, long long sC, int ldc) {
  extern __shared__ char smem[];
  const uint32_t sb = smem_u32(smem);
  const int tid = threadIdx.x;
  const int lane = tid & 31;
  const int wm = (tid >> 5) >> 2;   // 0..1
  const int wn = (tid >> 5) & 3;    // 0..3
  const int b = blockIdx.z;
  const size_t bm = (size_t)blockIdx.y * 128, bn = (size_t)blockIdx.x * 256;

  // -------- loader: thread t owns 3 rows: A(hi|lo) row, Bh row, Bl row ------
  const bf16* p0 = (tid < 128)
      ? Ah + (size_t)b * sA + (bm + tid) * (size_t)K
      : Al + (size_t)b * sA + (bm + tid - 128) * (size_t)K;
  const bf16* p1 = Bh + (size_t)b * sB + (bn + tid) * (size_t)K;
  const bf16* p2 = Bl + (size_t)b * sB + (bn + tid) * (size_t)K;
  const uint32_t s0 = sb + (uint32_t)((tid < 128) ? tid * LDM : TA + (tid - 128) * LDM);
  const uint32_t s1 = sb + (uint32_t)(2 * TA + tid * LDM);
  const uint32_t s2 = sb + (uint32_t)(2 * TA + TB + tid * LDM);

#define LOADST(c, s)                                                     \
  do {                                                                   \
    const uint32_t so_ = (uint32_t)(s) * STAGE;                          \
    const size_t ko_ = (size_t)(c) * 32;                                 \
    _Pragma("unroll") for (int ch_ = 0; ch_ < 4; ch_++)                  \
        cp16(s0 + so_ + ch_ * 16, p0 + ko_ + ch_ * 8);                   \
    _Pragma("unroll") for (int ch_ = 0; ch_ < 4; ch_++)                  \
        cp16(s1 + so_ + ch_ * 16, p1 + ko_ + ch_ * 8);                   \
    _Pragma("unroll") for (int ch_ = 0; ch_ < 4; ch_++)                  \
        cp16(s2 + so_ + ch_ * 16, p2 + ko_ + ch_ * 8);                   \
    cp_commit();                                                         \
  } while (0)

  // -------- fragment smem addresses (stage 0, kstep 0) ----------------------
  uint32_t aAh[4], aAl[4], aBh[4], aBl[4];
#pragma unroll
  for (int i = 0; i < 4; i++) {
    int row = wm * 64 + i * 16 + (lane & 15);
    uint32_t off = (uint32_t)(row * LDM + (lane >> 4) * 16);
    aAh[i] = sb + off;
    aAl[i] = sb + TA + off;
  }
#pragma unroll
  for (int j = 0; j < 4; j++) {
    int row = wn * 64 + j * 16 + (lane & 7) + ((lane >> 4) & 1) * 8;
    uint32_t off = (uint32_t)(row * LDM + ((lane >> 3) & 1) * 16);
    aBh[j] = sb + 2 * TA + off;
    aBl[j] = sb + 2 * TA + TB + off;
  }

  float acc[4][8][4];
#pragma unroll
  for (int i = 0; i < 4; i++)
#pragma unroll
    for (int j = 0; j < 8; j++)
#pragma unroll
      for (int r = 0; r < 4; r++) acc[i][j][r] = 0.f;

  const int NC = K >> 5;
  LOADST(0, 0);
  for (int c = 0; c < NC; c++) {
    const int s = c & 1;
    if (c + 1 < NC) { LOADST(c + 1, s ^ 1); cp_wait<1>(); }
    else            { cp_wait<0>(); }
    __syncthreads();
#pragma unroll
    for (int ks = 0; ks < 2; ks++) {
      const uint32_t soff = (uint32_t)s * STAGE + ks * 32;
      uint32_t fAh[4][4], fAl[4][4];
#pragma unroll
      for (int i = 0; i < 4; i++) {
        ldsm4(fAh[i], aAh[i] + soff);
        ldsm4(fAl[i], aAl[i] + soff);
      }
#pragma unroll
      for (int j = 0; j < 4; j++) {
        uint32_t fBh[4], fBl[4];
        ldsm4(fBh, aBh[j] + soff);
        ldsm4(fBl, aBl[j] + soff);
#pragma unroll
        for (int i = 0; i < 4; i++)
#pragma unroll
          for (int h = 0; h < 2; h++) {
            float* d = acc[i][j * 2 + h];
            mma16816(d, fAh[i], &fBh[h * 2]);
            mma16816(d, fAh[i], &fBl[h * 2]);
            mma16816(d, fAl[i], &fBh[h * 2]);
          }
      }
    }
    __syncthreads();
  }

  // -------- epilogue: direct global stores ----------------------------------
  const int l4 = lane >> 2, l2 = (lane & 3) * 2;
#pragma unroll
  for (int i = 0; i < 4; i++) {
#pragma unroll
    for (int j = 0; j < 8; j++) {
      const size_t row = bm + wm * 64 + i * 16 + l4;
      const size_t col = bn + wn * 64 + j * 8 + l2;
      float* a = acc[i][j];
      const size_t o = (size_t)b * sC + row * (size_t)ldc + col;
      if (EPI == 0) {
        float2 v0; v0.x = a[0]; v0.y = a[1];
        float2 v1; v1.x = a[2]; v1.y = a[3];
        *(float2*)(C + o) = v0;
        *(float2*)(C + o + 8 * (size_t)ldc) = v1;
      } else {
        float2 bv = *(const float2*)(bias + col);
        split2_store(Oh, Ol, o, fmaxf(a[0] + bv.x, 0.f), fmaxf(a[1] + bv.y, 0.f));
        split2_store(Oh, Ol, o + 8 * (size_t)ldc,
                     fmaxf(a[2] + bv.x, 0.f), fmaxf(a[3] + bv.y, 0.f));
      }
    }
  }
}

// ---------------- conversion kernels -----------------------------------------
__global__ void k_split(const float* __restrict__ x, bf16* __restrict__ oh,
                        bf16* __restrict__ ol, size_t n) {
  size_t i = (size_t)blockIdx.x * blockDim.x + threadIdx.x;
  if (i < n) split_store(oh, ol, i, x[i]);
}

__global__ void k_tsplit(const float* __restrict__ in, bf16* __restrict__ oh,
                         bf16* __restrict__ ol, int R, int Cc,
                         long long sIn, long long sOut) {
  __shared__ float t[32][33];
  const int b = blockIdx.z;
  const int r0 = blockIdx.y * 32, c0 = blockIdx.x * 32;
  const int tx = threadIdx.x, ty = threadIdx.y;
  const float* pin = in + (size_t)b * sIn;
#pragma unroll
  for (int k = 0; k < 4; k++)
    t[ty + 8 * k][tx] = pin[(size_t)(r0 + ty + 8 * k) * Cc + c0 + tx];
  __syncthreads();
#pragma unroll
  for (int k = 0; k < 4; k++) {
    float v = t[tx][ty + 8 * k];
    size_t o = (size_t)b * sOut + (size_t)(c0 + ty + 8 * k) * R + r0 + tx;
    split_store(oh, ol, o, v);
  }
}

__global__ void k_prow() {
  const int row = blockIdx.y;
  const int j = blockIdx.x * 256 + threadIdx.x;
  const float m = g_mrow[row], iz = g_izrow[row];
  const size_t o = (size_t)row * LB + j;
  float p = __expf(g_S[o] - m) * iz;
  split_store(g_prh, g_prl, o, p);
}

__global__ void k_pcolT() {
  __shared__ float t[32][33];
  const int b = blockIdx.z;
  const int i0 = blockIdx.y * 32, j0 = blockIdx.x * 32;
  const int tx = threadIdx.x, ty = threadIdx.y;
  const float* S = g_S + (size_t)b * LA * LB;
#pragma unroll
  for (int k = 0; k < 4; k++)
    t[ty + 8 * k][tx] = S[(size_t)(i0 + ty + 8 * k) * LB + j0 + tx];
  __syncthreads();
#pragma unroll
  for (int k = 0; k < 4; k++) {
    const int j = j0 + ty + 8 * k;
    float p = __expf(t[tx][ty + 8 * k] - g_mcol[b * LB + j]) * g_izcol[b * LB + j];
    size_t o = (size_t)b * LB * LA + (size_t)j * LA + i0 + tx;
    split_store(g_pch, g_pcl, o, p);
  }
}

// ---------------- softmax stats ----------------------------------------------
__device__ __forceinline__ void olcomb(float& m, float& z, float m2, float z2) {
  if (m2 > m) { z = z * __expf(m - m2) + z2; m = m2; }
  else        { z = z + z2 * __expf(m2 - m); }
}

__global__ void row_stats_kernel() {
  const int row = blockIdx.x;
  const float* s = g_S + (size_t)row * LB;
  float m = -3.0e38f, z = 0.f;
  for (int j = threadIdx.x; j < LB; j += 256) {
    float v = s[j];
    if (v > m) { z = z * __expf(m - v) + 1.f; m = v; }
    else       { z += __expf(v - m); }
  }
  __shared__ float sm[256], sz[256];
  sm[threadIdx.x] = m; sz[threadIdx.x] = z;
  __syncthreads();
  for (int st = 128; st > 0; st >>= 1) {
    if (threadIdx.x < st) {
      float m1 = sm[threadIdx.x], z1 = sz[threadIdx.x];
      olcomb(m1, z1, sm[threadIdx.x + st], sz[threadIdx.x + st]);
      sm[threadIdx.x] = m1; sz[threadIdx.x] = z1;
    }
    __syncthreads();
  }
  if (threadIdx.x == 0) { g_mrow[row] = sm[0]; g_izrow[row] = 1.f / sz[0]; }
}

__global__ void col_stats_kernel() {
  const int b = blockIdx.y;
  const int col = blockIdx.x * 128 + threadIdx.x;
  const float* s = g_S + (size_t)b * LA * LB + col;
  float m = -3.0e38f, z = 0.f;
  for (int i = threadIdx.y; i < LA; i += 8) {
    float v = s[(size_t)i * LB];
    if (v > m) { z = z * __expf(m - v) + 1.f; m = v; }
    else       { z += __expf(v - m); }
  }
  __shared__ float sm[8][128], sz[8][128];
  sm[threadIdx.y][threadIdx.x] = m; sz[threadIdx.y][threadIdx.x] = z;
  __syncthreads();
  if (threadIdx.y == 0) {
#pragma unroll
    for (int y = 1; y < 8; y++) olcomb(m, z, sm[y][threadIdx.x], sz[y][threadIdx.x]);
    g_mcol[b * LB + col] = m;
    g_izcol[b * LB + col] = 1.f / z;
  }
}

// ---------------- launch -----------------------------------------------------
#define GSA(T, v, sym) T* v; cudaGetSymbolAddress((void**)&v, sym)

extern "C" void kernel_launch(void* const* d_in, const int* in_sizes, int n_in,
                              void* d_out, int out_size) {
  const float* x1 = (const float*)d_in[0];
  const float* x2 = (const float*)d_in[1];
  const float* W1 = (const float*)d_in[2];
  const float* b1 = (const float*)d_in[3];
  const float* W2 = (const float*)d_in[4];
  const float* b2 = (const float*)d_in[5];
  const float* W3 = (const float*)d_in[6];
  const float* b3 = (const float*)d_in[7];
  float* out = (float*)d_out;
  float* alpha_out = out;                             // [B, LB, EMB]
  float* beta_out = out + (size_t)BATCH * LB * EMB;   // [B, LA, EMB]

  GSA(bf16, x1h, g_x1h); GSA(bf16, x1l, g_x1l);
  GSA(bf16, x2h, g_x2h); GSA(bf16, x2l, g_x2l);
  GSA(bf16, w1h, g_w1h); GSA(bf16, w1l, g_w1l);
  GSA(bf16, w2h, g_w2h); GSA(bf16, w2l, g_w2l);
  GSA(bf16, w3h, g_w3h); GSA(bf16, w3l, g_w3l);
  GSA(bf16, t1h, g_t1h); GSA(bf16, t1l, g_t1l);
  GSA(bf16, t2h, g_t2h); GSA(bf16, t2l, g_t2l);
  GSA(bf16, fah, g_fah); GSA(bf16, fal, g_fal);
  GSA(bf16, fbh, g_fbh); GSA(bf16, fbl, g_fbl);
  GSA(bf16, x1th, g_x1th); GSA(bf16, x1tl, g_x1tl);
  GSA(bf16, x2th, g_x2th); GSA(bf16, x2tl, g_x2tl);
  GSA(bf16, prh, g_prh); GSA(bf16, prl, g_prl);
  GSA(bf16, pch, g_pch); GSA(bf16, pcl, g_pcl);
  GSA(float, S, g_S);

  cudaFuncSetAttribute(gemm_mma<0>, cudaFuncAttributeMaxDynamicSharedMemorySize, SMEM_DYN);
  cudaFuncSetAttribute(gemm_mma<1>, cudaFuncAttributeMaxDynamicSharedMemorySize, SMEM_DYN);

  const size_t nx = (size_t)MTOT * EMB;
  dim3 t8(32, 8);

  // input conversions
  k_split<<<(unsigned)((nx + 255) / 256), 256>>>(x1, x1h, x1l, nx);
  k_split<<<(unsigned)((nx + 255) / 256), 256>>>(x2, x2h, x2l, nx);
  k_tsplit<<<dim3(HID / 32, EMB / 32, 1), t8>>>(W1, w1h, w1l, EMB, HID, 0, 0);
  k_tsplit<<<dim3(HID / 32, HID / 32, 1), t8>>>(W2, w2h, w2l, HID, HID, 0, 0);
  k_tsplit<<<dim3(HID / 32, HID / 32, 1), t8>>>(W3, w3h, w3l, HID, HID, 0, 0);
  k_tsplit<<<dim3(EMB / 32, LA / 32, BATCH), t8>>>(x1, x1th, x1tl, LA, EMB,
                                                   (long long)LA * EMB, (long long)EMB * LA);
  k_tsplit<<<dim3(EMB / 32, LB / 32, BATCH), t8>>>(x2, x2th, x2tl, LB, EMB,
                                                   (long long)LB * EMB, (long long)EMB * LB);

  dim3 gMLP(HID / 256, MTOT / 128, 1);  // (4, 64)
  // MLP x1 -> fa
  gemm_mma<1><<<gMLP, 256, SMEM_DYN>>>(x1h, x1l, w1h, w1l, EMB, 0, 0, nullptr, t1h, t1l, b1, 0, HID);
  gemm_mma<1><<<gMLP, 256, SMEM_DYN>>>(t1h, t1l, w2h, w2l, HID, 0, 0, nullptr, t2h, t2l, b2, 0, HID);
  gemm_mma<1><<<gMLP, 256, SMEM_DYN>>>(t2h, t2l, w3h, w3l, HID, 0, 0, nullptr, fah, fal, b3, 0, HID);
  // MLP x2 -> fb
  gemm_mma<1><<<gMLP, 256, SMEM_DYN>>>(x2h, x2l, w1h, w1l, EMB, 0, 0, nullptr, t1h, t1l, b1, 0, HID);
  gemm_mma<1><<<gMLP, 256, SMEM_DYN>>>(t1h, t1l, w2h, w2l, HID, 0, 0, nullptr, t2h, t2l, b2, 0, HID);
  gemm_mma<1><<<gMLP, 256, SMEM_DYN>>>(t2h, t2l, w3h, w3l, HID, 0, 0, nullptr, fbh, fbl, b3, 0, HID);

  // scores: S[b] = fa[b] @ fb[b]^T
  gemm_mma<0><<<dim3(LB / 256, LA / 128, BATCH), 256, SMEM_DYN>>>(
      fah, fal, fbh, fbl, HID, (long long)LA * HID, (long long)LB * HID,
      S, nullptr, nullptr, nullptr, (long long)LA * LB, LB);

  // softmax stats + probability conversion
  row_stats_kernel<<<BATCH * LA, 256>>>();
  col_stats_kernel<<<dim3(LB / 128, BATCH), dim3(128, 8)>>>();
  k_prow<<<dim3(LB / 256, BATCH * LA), 256>>>();
  k_pcolT<<<dim3(LB / 32, LA / 32, BATCH), t8>>>();

  // beta = Prow @ x2   (B operand = x2^T pairs)
  gemm_mma<0><<<dim3(EMB / 256, LA / 128, BATCH), 256, SMEM_DYN>>>(
      prh, prl, x2th, x2tl, LB, (long long)LA * LB, (long long)EMB * LB,
      beta_out, nullptr, nullptr, nullptr, (long long)LA * EMB, EMB);
  // alpha = PcolT @ x1 (B operand = x1^T pairs)
  gemm_mma<0><<<dim3(EMB / 256, LB / 128, BATCH), 256, SMEM_DYN>>>(
      pch, pcl, x1th, x1tl, LA, (long long)LB * LA, (long long)EMB * LA,
      alpha_out, nullptr, nullptr, nullptr, (long long)LB * EMB, EMB);
}

// round 6
// speedup vs baseline: 2.0555x; 1.1573x over previous
#include <cuda_runtime.h>
#include <cuda_fp16.h>
#include <stdint.h>
#include <math.h>

#define BATCH 2
#define LA 4096
#define LB 4096
#define EMB 1024
#define HID 1024
#define MTOT (BATCH * LA)
#define MALL (2 * MTOT)   // both MLPs merged: 16384 rows

typedef __half h16;

// ---------------- scratch (device globals: no alloc allowed) ----------------
__device__ h16 g_xh[(size_t)MALL * EMB], g_xl[(size_t)MALL * EMB];
__device__ h16 g_w1h[(size_t)HID * EMB], g_w1l[(size_t)HID * EMB];
__device__ h16 g_w2h[(size_t)HID * HID], g_w2l[(size_t)HID * HID];
__device__ h16 g_w3h[(size_t)HID * HID], g_w3l[(size_t)HID * HID];
__device__ h16 g_t1h[(size_t)MALL * HID], g_t1l[(size_t)MALL * HID];
__device__ h16 g_t2h[(size_t)MALL * HID], g_t2l[(size_t)MALL * HID];
__device__ h16 g_fh[(size_t)MALL * HID], g_fl[(size_t)MALL * HID];  // fa | fb
__device__ h16 g_x1t[(size_t)BATCH * EMB * LA];
__device__ h16 g_x2t[(size_t)BATCH * EMB * LB];
__device__ float g_S[(size_t)BATCH * LA * LB];
__device__ h16 g_prh[(size_t)BATCH * LA * LB], g_prl[(size_t)BATCH * LA * LB];
__device__ h16 g_pch[(size_t)BATCH * LB * LA], g_pcl[(size_t)BATCH * LB * LA];
__device__ float g_mrow[BATCH * LA], g_izrow[BATCH * LA];
__device__ float g_mcol[BATCH * LB], g_izcol[BATCH * LB];

// ---------------- ptx helpers ------------------------------------------------
__device__ __forceinline__ uint32_t smem_u32(const void* p) {
  uint32_t a;
  asm("{ .reg .u64 t; cvta.to.shared.u64 t, %1; cvt.u32.u64 %0, t; }"
      : "=r"(a) : "l"(p));
  return a;
}
__device__ __forceinline__ void cp16(uint32_t d, const void* s) {
  asm volatile("cp.async.cg.shared.global [%0], [%1], 16;" :: "r"(d), "l"(s));
}
__device__ __forceinline__ void cp_commit() {
  asm volatile("cp.async.commit_group;");
}
template <int N>
__device__ __forceinline__ void cp_wait() {
  asm volatile("cp.async.wait_group %0;" :: "n"(N));
}
__device__ __forceinline__ void ldsm4(uint32_t* r, uint32_t a) {
  asm volatile("ldmatrix.sync.aligned.m8n8.x4.shared.b16 {%0,%1,%2,%3}, [%4];"
               : "=r"(r[0]), "=r"(r[1]), "=r"(r[2]), "=r"(r[3]) : "r"(a));
}
__device__ __forceinline__ void mma16816(float* d, const uint32_t* a, const uint32_t* b) {
  asm volatile(
      "mma.sync.aligned.m16n8k16.row.col.f32.f16.f16.f32 "
      "{%0,%1,%2,%3}, {%4,%5,%6,%7}, {%8,%9}, {%0,%1,%2,%3};"
      : "+f"(d[0]), "+f"(d[1]), "+f"(d[2]), "+f"(d[3])
      : "r"(a[0]), "r"(a[1]), "r"(a[2]), "r"(a[3]), "r"(b[0]), "r"(b[1]));
}

__device__ __forceinline__ void split_store(h16* oh, h16* ol, size_t o, float v) {
  h16 h = __float2half_rn(v);
  oh[o] = h;
  ol[o] = __float2half_rn(v - __half2float(h));
}
__device__ __forceinline__ void split2_store(h16* oh, h16* ol, size_t o,
                                             float v0, float v1) {
  h16 h0 = __float2half_rn(v0), h1 = __float2half_rn(v1);
  __half2 hp; hp.x = h0; hp.y = h1;
  __half2 lp;
  lp.x = __float2half_rn(v0 - __half2float(h0));
  lp.y = __float2half_rn(v1 - __half2float(h1));
  *(__half2*)(oh + o) = hp;
  *(__half2*)(ol + o) = lp;
}

// ---------------- mma.sync GEMM core: C[128x256] = A @ B^T -------------------
// A as fp16 (hi,lo) pair, K-major. PASSES=3: B pair (AhBh+AhBl+AlBh).
// PASSES=2: B single (AhBh+AlBh). EPI 0: fp32 C. EPI 1: bias+relu -> pair.
static constexpr int LDM = 80;        // smem bytes per 32-h16 row (padded)
static constexpr int TAg = 128 * LDM; // 10240
static constexpr int TBg = 256 * LDM; // 20480
static constexpr int SMEM3 = 2 * (2 * TAg + 2 * TBg);  // 122880
static constexpr int SMEM2 = 2 * (2 * TAg + TBg);      // 81920

template <int EPI, int PASSES>
__device__ __forceinline__ void gemm_core(
    const h16* __restrict__ Ah, const h16* __restrict__ Al,
    const h16* __restrict__ Bh, const h16* __restrict__ Bl,
    int K, float* __restrict__ C, h16* __restrict__ Oh, h16* __restrict__ Ol,
    const float* __restrict__ bias, int ldc) {
  constexpr int STG = 2 * TAg + (PASSES == 3 ? 2 : 1) * TBg;
  extern __shared__ char smem[];
  const uint32_t sb = smem_u32(smem);
  const int tid = threadIdx.x;
  const int lane = tid & 31;
  const int wm = (tid >> 5) >> 2;   // 0..1
  const int wn = (tid >> 5) & 3;    // 0..3
  const size_t bm = (size_t)blockIdx.y * 128, bn = (size_t)blockIdx.x * 256;

  // loader: thread owns A(hi|lo) row + Bh row (+ Bl row if 3-pass)
  const h16* p0 = (tid < 128) ? Ah + (bm + tid) * (size_t)K
                              : Al + (bm + tid - 128) * (size_t)K;
  const h16* p1 = Bh + (bn + tid) * (size_t)K;
  const h16* p2 = (PASSES == 3) ? Bl + (bn + tid) * (size_t)K : nullptr;
  const uint32_t s0 = sb + (uint32_t)((tid < 128) ? tid * LDM : TAg + (tid - 128) * LDM);
  const uint32_t s1 = sb + (uint32_t)(2 * TAg + tid * LDM);
  const uint32_t s2 = sb + (uint32_t)(2 * TAg + TBg + tid * LDM);

#define LOADST(c, s)                                                     \
  do {                                                                   \
    const uint32_t so_ = (uint32_t)(s) * STG;                            \
    const size_t ko_ = (size_t)(c) * 32;                                 \
    _Pragma("unroll") for (int ch_ = 0; ch_ < 4; ch_++)                  \
        cp16(s0 + so_ + ch_ * 16, p0 + ko_ + ch_ * 8);                   \
    _Pragma("unroll") for (int ch_ = 0; ch_ < 4; ch_++)                  \
        cp16(s1 + so_ + ch_ * 16, p1 + ko_ + ch_ * 8);                   \
    if (PASSES == 3)                                                     \
      _Pragma("unroll") for (int ch_ = 0; ch_ < 4; ch_++)                \
          cp16(s2 + so_ + ch_ * 16, p2 + ko_ + ch_ * 8);                 \
    cp_commit();                                                         \
  } while (0)

  // fragment smem addresses (stage 0, kstep 0)
  uint32_t aAh[4], aAl[4], aBh[4], aBl[4];
#pragma unroll
  for (int i = 0; i < 4; i++) {
    int row = wm * 64 + i * 16 + (lane & 15);
    uint32_t off = (uint32_t)(row * LDM + (lane >> 4) * 16);
    aAh[i] = sb + off;
    aAl[i] = sb + TAg + off;
  }
#pragma unroll
  for (int j = 0; j < 4; j++) {
    int row = wn * 64 + j * 16 + (lane & 7) + ((lane >> 4) & 1) * 8;
    uint32_t off = (uint32_t)(row * LDM + ((lane >> 3) & 1) * 16);
    aBh[j] = sb + 2 * TAg + off;
    aBl[j] = sb + 2 * TAg + TBg + off;
  }

  float acc[4][8][4];
#pragma unroll
  for (int i = 0; i < 4; i++)
#pragma unroll
    for (int j = 0; j < 8; j++)
#pragma unroll
      for (int r = 0; r < 4; r++) acc[i][j][r] = 0.f;

  const int NC = K >> 5;
  LOADST(0, 0);
  for (int c = 0; c < NC; c++) {
    const int s = c & 1;
    if (c + 1 < NC) { LOADST(c + 1, s ^ 1); cp_wait<1>(); }
    else            { cp_wait<0>(); }
    __syncthreads();
#pragma unroll
    for (int ks = 0; ks < 2; ks++) {
      const uint32_t soff = (uint32_t)s * STG + ks * 32;
      uint32_t fAh[4][4], fAl[4][4];
#pragma unroll
      for (int i = 0; i < 4; i++) {
        ldsm4(fAh[i], aAh[i] + soff);
        ldsm4(fAl[i], aAl[i] + soff);
      }
#pragma unroll
      for (int j = 0; j < 4; j++) {
        uint32_t fBh[4], fBl[4];
        ldsm4(fBh, aBh[j] + soff);
        if (PASSES == 3) ldsm4(fBl, aBl[j] + soff);
#pragma unroll
        for (int i = 0; i < 4; i++)
#pragma unroll
          for (int hh = 0; hh < 2; hh++) {
            float* d = acc[i][j * 2 + hh];
            mma16816(d, fAh[i], &fBh[hh * 2]);
            if (PASSES == 3) mma16816(d, fAh[i], &fBl[hh * 2]);
            mma16816(d, fAl[i], &fBh[hh * 2]);
          }
      }
    }
    __syncthreads();
  }
#undef LOADST

  // epilogue
  const int l4 = lane >> 2, l2 = (lane & 3) * 2;
#pragma unroll
  for (int i = 0; i < 4; i++) {
#pragma unroll
    for (int j = 0; j < 8; j++) {
      const size_t row = bm + wm * 64 + i * 16 + l4;
      const size_t col = bn + wn * 64 + j * 8 + l2;
      float* a = acc[i][j];
      const size_t o = row * (size_t)ldc + col;
      if (EPI == 0) {
        float2 v0; v0.x = a[0]; v0.y = a[1];
        float2 v1; v1.x = a[2]; v1.y = a[3];
        *(float2*)(C + o) = v0;
        *(float2*)(C + o + 8 * (size_t)ldc) = v1;
      } else {
        float2 bv = *(const float2*)(bias + col);
        split2_store(Oh, Ol, o, fmaxf(a[0] + bv.x, 0.f), fmaxf(a[1] + bv.y, 0.f));
        split2_store(Oh, Ol, o + 8 * (size_t)ldc,
                     fmaxf(a[2] + bv.x, 0.f), fmaxf(a[3] + bv.y, 0.f));
      }
    }
  }
}

// generic wrapper (per-batch strides)
template <int EPI, int PASSES>
__global__ void __launch_bounds__(256, 1) gemm_mma(
    const h16* Ah, const h16* Al, const h16* Bh, const h16* Bl,
    int K, long long sA, long long sB,
    float* C, h16* Oh, h16* Ol, const float* bias, long long sC, int ldc) {
  const size_t b = blockIdx.z;
  gemm_core<EPI, PASSES>(
      Ah + b * sA, Al + b * sA, Bh + b * sB,
      (PASSES == 3) ? Bl + b * sB : nullptr, K,
      (EPI == 0) ? C + b * sC : nullptr,
      (EPI == 1) ? Oh + b * sC : nullptr,
      (EPI == 1) ? Ol + b * sC : nullptr, bias, ldc);
}

// fused beta+alpha: z=0,1 -> beta batches; z=2,3 -> alpha batches. 2-pass.
__global__ void __launch_bounds__(256, 1) attn_fused(
    const h16* __restrict__ x2t, const h16* __restrict__ x1t,
    float* __restrict__ beta, float* __restrict__ alpha) {
  const int z = blockIdx.z;
  const h16 *Ah, *Al, *Bh;
  float* C;
  if (z < 2) {
    Ah = g_prh + (size_t)z * LA * LB;
    Al = g_prl + (size_t)z * LA * LB;
    Bh = x2t + (size_t)z * EMB * LB;
    C = beta + (size_t)z * LA * EMB;
  } else {
    const int b = z - 2;
    Ah = g_pch + (size_t)b * LB * LA;
    Al = g_pcl + (size_t)b * LB * LA;
    Bh = x1t + (size_t)b * EMB * LA;
    C = alpha + (size_t)b * LB * EMB;
  }
  gemm_core<0, 2>(Ah, Al, Bh, nullptr, LB, C, nullptr, nullptr, nullptr, EMB);
}

// ---------------- conversion kernels -----------------------------------------
__global__ void k_split(const float* __restrict__ x, h16* __restrict__ oh,
                        h16* __restrict__ ol, size_t n) {
  size_t i = (size_t)blockIdx.x * blockDim.x + threadIdx.x;
  if (i < n) split_store(oh, ol, i, x[i]);
}

__global__ void k_tsplit(const float* __restrict__ in, h16* __restrict__ oh,
                         h16* __restrict__ ol, int R, int Cc) {
  __shared__ float t[32][33];
  const int r0 = blockIdx.y * 32, c0 = blockIdx.x * 32;
  const int tx = threadIdx.x, ty = threadIdx.y;
#pragma unroll
  for (int k = 0; k < 4; k++)
    t[ty + 8 * k][tx] = in[(size_t)(r0 + ty + 8 * k) * Cc + c0 + tx];
  __syncthreads();
#pragma unroll
  for (int k = 0; k < 4; k++) {
    float v = t[tx][ty + 8 * k];
    size_t o = (size_t)(c0 + ty + 8 * k) * R + r0 + tx;
    split_store(oh, ol, o, v);
  }
}

// transpose fp32 -> single fp16 (per batch)
__global__ void k_thalf(const float* __restrict__ in, h16* __restrict__ oh,
                        int R, int Cc, long long sIn, long long sOut) {
  __shared__ float t[32][33];
  const int b = blockIdx.z;
  const int r0 = blockIdx.y * 32, c0 = blockIdx.x * 32;
  const int tx = threadIdx.x, ty = threadIdx.y;
  const float* pin = in + (size_t)b * sIn;
#pragma unroll
  for (int k = 0; k < 4; k++)
    t[ty + 8 * k][tx] = pin[(size_t)(r0 + ty + 8 * k) * Cc + c0 + tx];
  __syncthreads();
#pragma unroll
  for (int k = 0; k < 4; k++) {
    size_t o = (size_t)b * sOut + (size_t)(c0 + ty + 8 * k) * R + r0 + tx;
    oh[o] = __float2half_rn(t[tx][ty + 8 * k]);
  }
}

__global__ void k_prow() {
  const int row = blockIdx.y;
  const int j = blockIdx.x * 256 + threadIdx.x;
  const float m = g_mrow[row], iz = g_izrow[row];
  const size_t o = (size_t)row * LB + j;
  float p = __expf(g_S[o] - m) * iz;
  split_store(g_prh, g_prl, o, p);
}

__global__ void k_pcolT() {
  __shared__ float t[32][33];
  const int b = blockIdx.z;
  const int i0 = blockIdx.y * 32, j0 = blockIdx.x * 32;
  const int tx = threadIdx.x, ty = threadIdx.y;
  const float* S = g_S + (size_t)b * LA * LB;
#pragma unroll
  for (int k = 0; k < 4; k++)
    t[ty + 8 * k][tx] = S[(size_t)(i0 + ty + 8 * k) * LB + j0 + tx];
  __syncthreads();
#pragma unroll
  for (int k = 0; k < 4; k++) {
    const int j = j0 + ty + 8 * k;
    float p = __expf(t[tx][ty + 8 * k] - g_mcol[b * LB + j]) * g_izcol[b * LB + j];
    size_t o = (size_t)b * LB * LA + (size_t)j * LA + i0 + tx;
    split_store(g_pch, g_pcl, o, p);
  }
}

// ---------------- softmax stats ----------------------------------------------
__device__ __forceinline__ void olcomb(float& m, float& z, float m2, float z2) {
  if (m2 > m) { z = z * __expf(m - m2) + z2; m = m2; }
  else        { z = z + z2 * __expf(m2 - m); }
}

__global__ void row_stats_kernel() {
  const int row = blockIdx.x;
  const float* s = g_S + (size_t)row * LB;
  float m = -3.0e38f, z = 0.f;
  for (int j = threadIdx.x; j < LB; j += 256) {
    float v = s[j];
    if (v > m) { z = z * __expf(m - v) + 1.f; m = v; }
    else       { z += __expf(v - m); }
  }
  __shared__ float sm[256], sz[256];
  sm[threadIdx.x] = m; sz[threadIdx.x] = z;
  __syncthreads();
  for (int st = 128; st > 0; st >>= 1) {
    if (threadIdx.x < st) {
      float m1 = sm[threadIdx.x], z1 = sz[threadIdx.x];
      olcomb(m1, z1, sm[threadIdx.x + st], sz[threadIdx.x + st]);
      sm[threadIdx.x] = m1; sz[threadIdx.x] = z1;
    }
    __syncthreads();
  }
  if (threadIdx.x == 0) { g_mrow[row] = sm[0]; g_izrow[row] = 1.f / sz[0]; }
}

__global__ void col_stats_kernel() {
  const int b = blockIdx.y;
  const int col = blockIdx.x * 128 + threadIdx.x;
  const float* s = g_S + (size_t)b * LA * LB + col;
  float m = -3.0e38f, z = 0.f;
  for (int i = threadIdx.y; i < LA; i += 8) {
    float v = s[(size_t)i * LB];
    if (v > m) { z = z * __expf(m - v) + 1.f; m = v; }
    else       { z += __expf(v - m); }
  }
  __shared__ float sm[8][128], sz[8][128];
  sm[threadIdx.y][threadIdx.x] = m; sz[threadIdx.y][threadIdx.x] = z;
  __syncthreads();
  if (threadIdx.y == 0) {
#pragma unroll
    for (int y = 1; y < 8; y++) olcomb(m, z, sm[y][threadIdx.x], sz[y][threadIdx.x]);
    g_mcol[b * LB + col] = m;
    g_izcol[b * LB + col] = 1.f / z;
  }
}

// ---------------- launch -----------------------------------------------------
#define GSA(T, v, sym) T* v; cudaGetSymbolAddress((void**)&v, sym)

extern "C" void kernel_launch(void* const* d_in, const int* in_sizes, int n_in,
                              void* d_out, int out_size) {
  const float* x1 = (const float*)d_in[0];
  const float* x2 = (const float*)d_in[1];
  const float* W1 = (const float*)d_in[2];
  const float* b1 = (const float*)d_in[3];
  const float* W2 = (const float*)d_in[4];
  const float* b2 = (const float*)d_in[5];
  const float* W3 = (const float*)d_in[6];
  const float* b3 = (const float*)d_in[7];
  float* out = (float*)d_out;
  float* alpha_out = out;                             // [B, LB, EMB]
  float* beta_out = out + (size_t)BATCH * LB * EMB;   // [B, LA, EMB]

  GSA(h16, xh, g_xh); GSA(h16, xl, g_xl);
  GSA(h16, w1h, g_w1h); GSA(h16, w1l, g_w1l);
  GSA(h16, w2h, g_w2h); GSA(h16, w2l, g_w2l);
  GSA(h16, w3h, g_w3h); GSA(h16, w3l, g_w3l);
  GSA(h16, t1h, g_t1h); GSA(h16, t1l, g_t1l);
  GSA(h16, t2h, g_t2h); GSA(h16, t2l, g_t2l);
  GSA(h16, fh, g_fh); GSA(h16, fl, g_fl);
  GSA(h16, x1t, g_x1t); GSA(h16, x2t, g_x2t);
  GSA(float, S, g_S);

  cudaFuncSetAttribute(gemm_mma<0, 3>, cudaFuncAttributeMaxDynamicSharedMemorySize, SMEM3);
  cudaFuncSetAttribute(gemm_mma<1, 3>, cudaFuncAttributeMaxDynamicSharedMemorySize, SMEM3);
  cudaFuncSetAttribute(attn_fused, cudaFuncAttributeMaxDynamicSharedMemorySize, SMEM2);

  const size_t nx = (size_t)MTOT * EMB;
  dim3 t8(32, 8);

  // input conversions: x1 -> rows [0, 8192), x2 -> rows [8192, 16384)
  k_split<<<(unsigned)((nx + 255) / 256), 256>>>(x1, xh, xl, nx);
  k_split<<<(unsigned)((nx + 255) / 256), 256>>>(x2, xh + nx, xl + nx, nx);
  k_tsplit<<<dim3(HID / 32, EMB / 32), t8>>>(W1, w1h, w1l, EMB, HID);
  k_tsplit<<<dim3(HID / 32, HID / 32), t8>>>(W2, w2h, w2l, HID, HID);
  k_tsplit<<<dim3(HID / 32, HID / 32), t8>>>(W3, w3h, w3l, HID, HID);
  k_thalf<<<dim3(EMB / 32, LA / 32, BATCH), t8>>>(x1, x1t, LA, EMB,
                                                  (long long)LA * EMB, (long long)EMB * LA);
  k_thalf<<<dim3(EMB / 32, LB / 32, BATCH), t8>>>(x2, x2t, LB, EMB,
                                                  (long long)LB * EMB, (long long)EMB * LB);

  // merged MLP (both inputs, both batches): M = 16384
  dim3 gMLP(HID / 256, MALL / 128, 1);  // (4, 128)
  gemm_mma<1, 3><<<gMLP, 256, SMEM3>>>(xh, xl, w1h, w1l, EMB, 0, 0,
                                       nullptr, t1h, t1l, b1, 0, HID);
  gemm_mma<1, 3><<<gMLP, 256, SMEM3>>>(t1h, t1l, w2h, w2l, HID, 0, 0,
                                       nullptr, t2h, t2l, b2, 0, HID);
  gemm_mma<1, 3><<<gMLP, 256, SMEM3>>>(t2h, t2l, w3h, w3l, HID, 0, 0,
                                       nullptr, fh, fl, b3, 0, HID);

  // scores: S[b] = fa[b] @ fb[b]^T ; fa = rows [0,8192), fb = rows [8192,16384)
  const h16* fah = fh;
  const h16* fal = fl;
  const h16* fbh = fh + (size_t)MTOT * HID;
  const h16* fbl = fl + (size_t)MTOT * HID;
  gemm_mma<0, 3><<<dim3(LB / 256, LA / 128, BATCH), 256, SMEM3>>>(
      fah, fal, fbh, fbl, HID, (long long)LA * HID, (long long)LB * HID,
      S, nullptr, nullptr, nullptr, (long long)LA * LB, LB);

  // softmax stats + probability conversion
  row_stats_kernel<<<BATCH * LA, 256>>>();
  col_stats_kernel<<<dim3(LB / 128, BATCH), dim3(128, 8)>>>();
  k_prow<<<dim3(LB / 256, BATCH * LA), 256>>>();
  k_pcolT<<<dim3(LB / 32, LA / 32, BATCH), t8>>>();

  // fused beta+alpha (2-pass): z=0,1 beta; z=2,3 alpha
  attn_fused<<<dim3(EMB / 256, LA / 128, 4), 256, SMEM2>>>(
      x2t, x1t, beta_out, alpha_out);
}

// round 7
// speedup vs baseline: 2.3683x; 1.1522x over previous
#include <cuda_runtime.h>
#include <cuda_fp16.h>
#include <stdint.h>
#include <math.h>

#define BATCH 2
#define LA 4096
#define LB 4096
#define EMB 1024
#define HID 1024
#define MTOT (BATCH * LA)
#define MALL (2 * MTOT)   // both MLPs merged: 16384 rows

typedef __half h16;

// ---------------- scratch (device globals: no alloc allowed) ----------------
__device__ h16 g_xh[(size_t)MALL * EMB], g_xl[(size_t)MALL * EMB];
__device__ h16 g_w1h[(size_t)HID * EMB], g_w1l[(size_t)HID * EMB];
__device__ h16 g_w2h[(size_t)HID * HID], g_w2l[(size_t)HID * HID];
__device__ h16 g_w3h[(size_t)HID * HID], g_w3l[(size_t)HID * HID];
__device__ h16 g_t1h[(size_t)MALL * HID], g_t1l[(size_t)MALL * HID];
__device__ h16 g_t2h[(size_t)MALL * HID], g_t2l[(size_t)MALL * HID];
__device__ h16 g_fh[(size_t)MALL * HID], g_fl[(size_t)MALL * HID];  // fa | fb
__device__ h16 g_x1t[(size_t)BATCH * EMB * LA];
__device__ h16 g_x2t[(size_t)BATCH * EMB * LB];
__device__ float g_S[(size_t)BATCH * LA * LB];
__device__ h16 g_pr[(size_t)BATCH * LA * LB];   // row-softmax(S)
__device__ h16 g_pc[(size_t)BATCH * LB * LA];   // col-softmax(S)^T
__device__ float g_mcol[BATCH * LB], g_izcol[BATCH * LB];

// ---------------- ptx helpers ------------------------------------------------
__device__ __forceinline__ uint32_t smem_u32(const void* p) {
  uint32_t a;
  asm("{ .reg .u64 t; cvta.to.shared.u64 t, %1; cvt.u32.u64 %0, t; }"
      : "=r"(a) : "l"(p));
  return a;
}
__device__ __forceinline__ void cp16(uint32_t d, const void* s) {
  asm volatile("cp.async.cg.shared.global [%0], [%1], 16;" :: "r"(d), "l"(s));
}
__device__ __forceinline__ void cp_commit() {
  asm volatile("cp.async.commit_group;");
}
template <int N>
__device__ __forceinline__ void cp_wait() {
  asm volatile("cp.async.wait_group %0;" :: "n"(N));
}
__device__ __forceinline__ void ldsm4(uint32_t* r, uint32_t a) {
  asm volatile("ldmatrix.sync.aligned.m8n8.x4.shared.b16 {%0,%1,%2,%3}, [%4];"
               : "=r"(r[0]), "=r"(r[1]), "=r"(r[2]), "=r"(r[3]) : "r"(a));
}
__device__ __forceinline__ void mma16816(float* d, const uint32_t* a, const uint32_t* b) {
  asm volatile(
      "mma.sync.aligned.m16n8k16.row.col.f32.f16.f16.f32 "
      "{%0,%1,%2,%3}, {%4,%5,%6,%7}, {%8,%9}, {%0,%1,%2,%3};"
      : "+f"(d[0]), "+f"(d[1]), "+f"(d[2]), "+f"(d[3])
      : "r"(a[0]), "r"(a[1]), "r"(a[2]), "r"(a[3]), "r"(b[0]), "r"(b[1]));
}

__device__ __forceinline__ void split_store(h16* oh, h16* ol, size_t o, float v) {
  h16 h = __float2half_rn(v);
  oh[o] = h;
  ol[o] = __float2half_rn(v - __half2float(h));
}
__device__ __forceinline__ void split2_store(h16* oh, h16* ol, size_t o,
                                             float v0, float v1) {
  h16 h0 = __float2half_rn(v0), h1 = __float2half_rn(v1);
  __half2 hp; hp.x = h0; hp.y = h1;
  __half2 lp;
  lp.x = __float2half_rn(v0 - __half2float(h0));
  lp.y = __float2half_rn(v1 - __half2float(h1));
  *(__half2*)(oh + o) = hp;
  *(__half2*)(ol + o) = lp;
}

// ---------------- mma.sync GEMM core: C[128x256] = A @ B^T -------------------
// PASSES=3: A pair, B pair (AhBh + AhBl + AlBh).
// PASSES=1: A single, B single (AhBh).
// EPI 0: fp32 C. EPI 1: bias+relu -> fp16 pair.
static constexpr int LDM = 80;        // smem bytes per 32-h16 row (padded)
static constexpr int TAg = 128 * LDM; // 10240
static constexpr int TBg = 256 * LDM; // 20480
static constexpr int SMEM3 = 2 * (2 * TAg + 2 * TBg);  // 122880
static constexpr int SMEM1 = 2 * (TAg + TBg);          // 61440

template <int EPI, int PASSES>
__device__ __forceinline__ void gemm_core(
    const h16* __restrict__ Ah, const h16* __restrict__ Al,
    const h16* __restrict__ Bh, const h16* __restrict__ Bl,
    int K, float* __restrict__ C, h16* __restrict__ Oh, h16* __restrict__ Ol,
    const float* __restrict__ bias, int ldc) {
  constexpr int NTA = (PASSES >= 2) ? 2 : 1;
  constexpr int NTB = (PASSES == 3) ? 2 : 1;
  constexpr int STG = NTA * TAg + NTB * TBg;
  extern __shared__ char smem[];
  const uint32_t sb = smem_u32(smem);
  const int tid = threadIdx.x;
  const int lane = tid & 31;
  const int wm = (tid >> 5) >> 2;   // 0..1
  const int wn = (tid >> 5) & 3;    // 0..3
  const size_t bm = (size_t)blockIdx.y * 128, bn = (size_t)blockIdx.x * 256;

  // loader rows
  const h16* p0;
  uint32_t s0;
  if (PASSES >= 2) {
    p0 = (tid < 128) ? Ah + (bm + tid) * (size_t)K
                     : Al + (bm + tid - 128) * (size_t)K;
    s0 = sb + (uint32_t)((tid < 128) ? tid * LDM : TAg + (tid - 128) * LDM);
  } else {
    p0 = Ah + (bm + (tid & 127)) * (size_t)K;   // only tid<128 stores
    s0 = sb + (uint32_t)((tid & 127) * LDM);
  }
  const h16* p1 = Bh + (bn + tid) * (size_t)K;
  const h16* p2 = (PASSES == 3) ? Bl + (bn + tid) * (size_t)K : nullptr;
  const uint32_t s1 = sb + (uint32_t)(NTA * TAg + tid * LDM);
  const uint32_t s2 = sb + (uint32_t)(NTA * TAg + TBg + tid * LDM);

#define LOADST(c, s)                                                     \
  do {                                                                   \
    const uint32_t so_ = (uint32_t)(s) * STG;                            \
    const size_t ko_ = (size_t)(c) * 32;                                 \
    if (PASSES >= 2 || tid < 128)                                        \
      _Pragma("unroll") for (int ch_ = 0; ch_ < 4; ch_++)                \
          cp16(s0 + so_ + ch_ * 16, p0 + ko_ + ch_ * 8);                 \
    _Pragma("unroll") for (int ch_ = 0; ch_ < 4; ch_++)                  \
        cp16(s1 + so_ + ch_ * 16, p1 + ko_ + ch_ * 8);                   \
    if (PASSES == 3)                                                     \
      _Pragma("unroll") for (int ch_ = 0; ch_ < 4; ch_++)                \
          cp16(s2 + so_ + ch_ * 16, p2 + ko_ + ch_ * 8);                 \
    cp_commit();                                                         \
  } while (0)

  // fragment smem addresses (stage 0, kstep 0)
  uint32_t aAh[4], aAl[4], aBh[4], aBl[4];
#pragma unroll
  for (int i = 0; i < 4; i++) {
    int row = wm * 64 + i * 16 + (lane & 15);
    uint32_t off = (uint32_t)(row * LDM + (lane >> 4) * 16);
    aAh[i] = sb + off;
    aAl[i] = sb + TAg + off;
  }
#pragma unroll
  for (int j = 0; j < 4; j++) {
    int row = wn * 64 + j * 16 + (lane & 7) + ((lane >> 4) & 1) * 8;
    uint32_t off = (uint32_t)(row * LDM + ((lane >> 3) & 1) * 16);
    aBh[j] = sb + NTA * TAg + off;
    aBl[j] = sb + NTA * TAg + TBg + off;
  }

  float acc[4][8][4];
#pragma unroll
  for (int i = 0; i < 4; i++)
#pragma unroll
    for (int j = 0; j < 8; j++)
#pragma unroll
      for (int r = 0; r < 4; r++) acc[i][j][r] = 0.f;

  const int NC = K >> 5;
  LOADST(0, 0);
  for (int c = 0; c < NC; c++) {
    const int s = c & 1;
    if (c + 1 < NC) { LOADST(c + 1, s ^ 1); cp_wait<1>(); }
    else            { cp_wait<0>(); }
    __syncthreads();
#pragma unroll
    for (int ks = 0; ks < 2; ks++) {
      const uint32_t soff = (uint32_t)s * STG + ks * 32;
      uint32_t fAh[4][4], fAl[4][4];
#pragma unroll
      for (int i = 0; i < 4; i++) {
        ldsm4(fAh[i], aAh[i] + soff);
        if (PASSES >= 2) ldsm4(fAl[i], aAl[i] + soff);
      }
#pragma unroll
      for (int j = 0; j < 4; j++) {
        uint32_t fBh[4], fBl[4];
        ldsm4(fBh, aBh[j] + soff);
        if (PASSES == 3) ldsm4(fBl, aBl[j] + soff);
#pragma unroll
        for (int i = 0; i < 4; i++)
#pragma unroll
          for (int hh = 0; hh < 2; hh++) {
            float* d = acc[i][j * 2 + hh];
            mma16816(d, fAh[i], &fBh[hh * 2]);
            if (PASSES == 3) mma16816(d, fAh[i], &fBl[hh * 2]);
            if (PASSES >= 2) mma16816(d, fAl[i], &fBh[hh * 2]);
          }
      }
    }
    __syncthreads();
  }
#undef LOADST

  // epilogue
  const int l4 = lane >> 2, l2 = (lane & 3) * 2;
#pragma unroll
  for (int i = 0; i < 4; i++) {
#pragma unroll
    for (int j = 0; j < 8; j++) {
      const size_t row = bm + wm * 64 + i * 16 + l4;
      const size_t col = bn + wn * 64 + j * 8 + l2;
      float* a = acc[i][j];
      const size_t o = row * (size_t)ldc + col;
      if (EPI == 0) {
        float2 v0; v0.x = a[0]; v0.y = a[1];
        float2 v1; v1.x = a[2]; v1.y = a[3];
        *(float2*)(C + o) = v0;
        *(float2*)(C + o + 8 * (size_t)ldc) = v1;
      } else {
        float2 bv = *(const float2*)(bias + col);
        split2_store(Oh, Ol, o, fmaxf(a[0] + bv.x, 0.f), fmaxf(a[1] + bv.y, 0.f));
        split2_store(Oh, Ol, o + 8 * (size_t)ldc,
                     fmaxf(a[2] + bv.x, 0.f), fmaxf(a[3] + bv.y, 0.f));
      }
    }
  }
}

// generic wrapper (per-batch strides)
template <int EPI, int PASSES>
__global__ void __launch_bounds__(256, 1) gemm_mma(
    const h16* Ah, const h16* Al, const h16* Bh, const h16* Bl,
    int K, long long sA, long long sB,
    float* C, h16* Oh, h16* Ol, const float* bias, long long sC, int ldc) {
  const size_t b = blockIdx.z;
  gemm_core<EPI, PASSES>(
      Ah + b * sA, (PASSES >= 2) ? Al + b * sA : nullptr, Bh + b * sB,
      (PASSES == 3) ? Bl + b * sB : nullptr, K,
      (EPI == 0) ? C + b * sC : nullptr,
      (EPI == 1) ? Oh + b * sC : nullptr,
      (EPI == 1) ? Ol + b * sC : nullptr, bias, ldc);
}

// fused beta+alpha, 1-pass: z=0,1 -> beta batches; z=2,3 -> alpha batches
__global__ void __launch_bounds__(256, 1) attn_fused(
    const h16* __restrict__ x2t, const h16* __restrict__ x1t,
    float* __restrict__ beta, float* __restrict__ alpha) {
  const int z = blockIdx.z;
  const h16 *A, *Bh;
  float* C;
  if (z < 2) {
    A = g_pr + (size_t)z * LA * LB;
    Bh = x2t + (size_t)z * EMB * LB;
    C = beta + (size_t)z * LA * EMB;
  } else {
    const int b = z - 2;
    A = g_pc + (size_t)b * LB * LA;
    Bh = x1t + (size_t)b * EMB * LA;
    C = alpha + (size_t)b * LB * EMB;
  }
  gemm_core<0, 1>(A, nullptr, Bh, nullptr, LB, C, nullptr, nullptr, nullptr, EMB);
}

// ---------------- conversion kernels -----------------------------------------
__global__ void k_split(const float* __restrict__ x, h16* __restrict__ oh,
                        h16* __restrict__ ol, size_t n) {
  size_t i = (size_t)blockIdx.x * blockDim.x + threadIdx.x;
  if (i < n) split_store(oh, ol, i, x[i]);
}

__global__ void k_tsplit(const float* __restrict__ in, h16* __restrict__ oh,
                         h16* __restrict__ ol, int R, int Cc) {
  __shared__ float t[32][33];
  const int r0 = blockIdx.y * 32, c0 = blockIdx.x * 32;
  const int tx = threadIdx.x, ty = threadIdx.y;
#pragma unroll
  for (int k = 0; k < 4; k++)
    t[ty + 8 * k][tx] = in[(size_t)(r0 + ty + 8 * k) * Cc + c0 + tx];
  __syncthreads();
#pragma unroll
  for (int k = 0; k < 4; k++) {
    float v = t[tx][ty + 8 * k];
    size_t o = (size_t)(c0 + ty + 8 * k) * R + r0 + tx;
    split_store(oh, ol, o, v);
  }
}

// transpose fp32 -> single fp16 (per batch)
__global__ void k_thalf(const float* __restrict__ in, h16* __restrict__ oh,
                        int R, int Cc, long long sIn, long long sOut) {
  __shared__ float t[32][33];
  const int b = blockIdx.z;
  const int r0 = blockIdx.y * 32, c0 = blockIdx.x * 32;
  const int tx = threadIdx.x, ty = threadIdx.y;
  const float* pin = in + (size_t)b * sIn;
#pragma unroll
  for (int k = 0; k < 4; k++)
    t[ty + 8 * k][tx] = pin[(size_t)(r0 + ty + 8 * k) * Cc + c0 + tx];
  __syncthreads();
#pragma unroll
  for (int k = 0; k < 4; k++) {
    size_t o = (size_t)b * sOut + (size_t)(c0 + ty + 8 * k) * R + r0 + tx;
    oh[o] = __float2half_rn(t[tx][ty + 8 * k]);
  }
}

// ---------------- softmax -----------------------------------------------------
__device__ __forceinline__ void olcomb(float& m, float& z, float m2, float z2) {
  if (m2 > m) { z = z * __expf(m - m2) + z2; m = m2; }
  else        { z = z + z2 * __expf(m2 - m); }
}

// fused: row stats + exp-normalize -> g_pr (fp16)
__global__ void row_softmax_kernel() {
  const int row = blockIdx.x;
  const float* s = g_S + (size_t)row * LB;
  float m = -3.0e38f, z = 0.f;
  for (int j = threadIdx.x; j < LB; j += 256) {
    float v = s[j];
    if (v > m) { z = z * __expf(m - v) + 1.f; m = v; }
    else       { z += __expf(v - m); }
  }
  __shared__ float sm[256], sz[256];
  sm[threadIdx.x] = m; sz[threadIdx.x] = z;
  __syncthreads();
  for (int st = 128; st > 0; st >>= 1) {
    if (threadIdx.x < st) {
      float m1 = sm[threadIdx.x], z1 = sz[threadIdx.x];
      olcomb(m1, z1, sm[threadIdx.x + st], sz[threadIdx.x + st]);
      sm[threadIdx.x] = m1; sz[threadIdx.x] = z1;
    }
    __syncthreads();
  }
  const float mm = sm[0], iz = 1.f / sz[0];
  h16* p = g_pr + (size_t)row * LB;
  for (int j = threadIdx.x; j < LB; j += 256)
    p[j] = __float2half_rn(__expf(s[j] - mm) * iz);
}

__global__ void col_stats_kernel() {
  const int b = blockIdx.y;
  const int col = blockIdx.x * 128 + threadIdx.x;
  const float* s = g_S + (size_t)b * LA * LB + col;
  float m = -3.0e38f, z = 0.f;
  for (int i = threadIdx.y; i < LA; i += 8) {
    float v = s[(size_t)i * LB];
    if (v > m) { z = z * __expf(m - v) + 1.f; m = v; }
    else       { z += __expf(v - m); }
  }
  __shared__ float sm[8][128], sz[8][128];
  sm[threadIdx.y][threadIdx.x] = m; sz[threadIdx.y][threadIdx.x] = z;
  __syncthreads();
  if (threadIdx.y == 0) {
#pragma unroll
    for (int y = 1; y < 8; y++) olcomb(m, z, sm[y][threadIdx.x], sz[y][threadIdx.x]);
    g_mcol[b * LB + col] = m;
    g_izcol[b * LB + col] = 1.f / z;
  }
}

// col-softmax + transpose -> g_pc (fp16)
__global__ void k_pcolT() {
  __shared__ float t[32][33];
  const int b = blockIdx.z;
  const int i0 = blockIdx.y * 32, j0 = blockIdx.x * 32;
  const int tx = threadIdx.x, ty = threadIdx.y;
  const float* S = g_S + (size_t)b * LA * LB;
#pragma unroll
  for (int k = 0; k < 4; k++)
    t[ty + 8 * k][tx] = S[(size_t)(i0 + ty + 8 * k) * LB + j0 + tx];
  __syncthreads();
#pragma unroll
  for (int k = 0; k < 4; k++) {
    const int j = j0 + ty + 8 * k;
    float p = __expf(t[tx][ty + 8 * k] - g_mcol[b * LB + j]) * g_izcol[b * LB + j];
    size_t o = (size_t)b * LB * LA + (size_t)j * LA + i0 + tx;
    g_pc[o] = __float2half_rn(p);
  }
}

// ---------------- launch -----------------------------------------------------
#define GSA(T, v, sym) T* v; cudaGetSymbolAddress((void**)&v, sym)

extern "C" void kernel_launch(void* const* d_in, const int* in_sizes, int n_in,
                              void* d_out, int out_size) {
  const float* x1 = (const float*)d_in[0];
  const float* x2 = (const float*)d_in[1];
  const float* W1 = (const float*)d_in[2];
  const float* b1 = (const float*)d_in[3];
  const float* W2 = (const float*)d_in[4];
  const float* b2 = (const float*)d_in[5];
  const float* W3 = (const float*)d_in[6];
  const float* b3 = (const float*)d_in[7];
  float* out = (float*)d_out;
  float* alpha_out = out;                             // [B, LB, EMB]
  float* beta_out = out + (size_t)BATCH * LB * EMB;   // [B, LA, EMB]

  GSA(h16, xh, g_xh); GSA(h16, xl, g_xl);
  GSA(h16, w1h, g_w1h); GSA(h16, w1l, g_w1l);
  GSA(h16, w2h, g_w2h); GSA(h16, w2l, g_w2l);
  GSA(h16, w3h, g_w3h); GSA(h16, w3l, g_w3l);
  GSA(h16, t1h, g_t1h); GSA(h16, t1l, g_t1l);
  GSA(h16, t2h, g_t2h); GSA(h16, t2l, g_t2l);
  GSA(h16, fh, g_fh); GSA(h16, fl, g_fl);
  GSA(h16, x1t, g_x1t); GSA(h16, x2t, g_x2t);
  GSA(float, S, g_S);

  cudaFuncSetAttribute(gemm_mma<0, 3>, cudaFuncAttributeMaxDynamicSharedMemorySize, SMEM3);
  cudaFuncSetAttribute(gemm_mma<1, 3>, cudaFuncAttributeMaxDynamicSharedMemorySize, SMEM3);
  cudaFuncSetAttribute(attn_fused, cudaFuncAttributeMaxDynamicSharedMemorySize, SMEM1);

  const size_t nx = (size_t)MTOT * EMB;
  dim3 t8(32, 8);

  // input conversions: x1 -> rows [0, 8192), x2 -> rows [8192, 16384)
  k_split<<<(unsigned)((nx + 255) / 256), 256>>>(x1, xh, xl, nx);
  k_split<<<(unsigned)((nx + 255) / 256), 256>>>(x2, xh + nx, xl + nx, nx);
  k_tsplit<<<dim3(HID / 32, EMB / 32), t8>>>(W1, w1h, w1l, EMB, HID);
  k_tsplit<<<dim3(HID / 32, HID / 32), t8>>>(W2, w2h, w2l, HID, HID);
  k_tsplit<<<dim3(HID / 32, HID / 32), t8>>>(W3, w3h, w3l, HID, HID);
  k_thalf<<<dim3(EMB / 32, LA / 32, BATCH), t8>>>(x1, x1t, LA, EMB,
                                                  (long long)LA * EMB, (long long)EMB * LA);
  k_thalf<<<dim3(EMB / 32, LB / 32, BATCH), t8>>>(x2, x2t, LB, EMB,
                                                  (long long)LB * EMB, (long long)EMB * LB);

  // merged MLP (both inputs, both batches): M = 16384
  dim3 gMLP(HID / 256, MALL / 128, 1);  // (4, 128)
  gemm_mma<1, 3><<<gMLP, 256, SMEM3>>>(xh, xl, w1h, w1l, EMB, 0, 0,
                                       nullptr, t1h, t1l, b1, 0, HID);
  gemm_mma<1, 3><<<gMLP, 256, SMEM3>>>(t1h, t1l, w2h, w2l, HID, 0, 0,
                                       nullptr, t2h, t2l, b2, 0, HID);
  gemm_mma<1, 3><<<gMLP, 256, SMEM3>>>(t2h, t2l, w3h, w3l, HID, 0, 0,
                                       nullptr, fh, fl, b3, 0, HID);

  // scores: S[b] = fa[b] @ fb[b]^T ; fa = rows [0,8192), fb = rows [8192,16384)
  const h16* fah = fh;
  const h16* fal = fl;
  const h16* fbh = fh + (size_t)MTOT * HID;
  const h16* fbl = fl + (size_t)MTOT * HID;
  gemm_mma<0, 3><<<dim3(LB / 256, LA / 128, BATCH), 256, SMEM3>>>(
      fah, fal, fbh, fbl, HID, (long long)LA * HID, (long long)LB * HID,
      S, nullptr, nullptr, nullptr, (long long)LA * LB, LB);

  // softmax: fused row stats+normalize; col stats then transpose-normalize
  row_softmax_kernel<<<BATCH * LA, 256>>>();
  col_stats_kernel<<<dim3(LB / 128, BATCH), dim3(128, 8)>>>();
  k_pcolT<<<dim3(LB / 32, LA / 32, BATCH), t8>>>();

  // fused beta+alpha (1-pass): z=0,1 beta; z=2,3 alpha
  attn_fused<<<dim3(EMB / 256, LA / 128, 4), 256, SMEM1>>>(
      x2t, x1t, beta_out, alpha_out);
}

// round 8
// speedup vs baseline: 2.5986x; 1.0972x over previous
#include <cuda_runtime.h>
#include <cuda_fp16.h>
#include <stdint.h>
#include <math.h>

#define BATCH 2
#define LA 4096
#define LB 4096
#define EMB 1024
#define HID 1024
#define MTOT (BATCH * LA)
#define MALL (2 * MTOT)   // both MLPs merged: 16384 rows

typedef __half h16;

// ---------------- scratch (device globals: no alloc allowed) ----------------
__device__ h16 g_xh[(size_t)MALL * EMB], g_xl[(size_t)MALL * EMB];
__device__ h16 g_w1h[(size_t)HID * EMB], g_w1l[(size_t)HID * EMB];
__device__ h16 g_w2h[(size_t)HID * HID], g_w2l[(size_t)HID * HID];
__device__ h16 g_w3h[(size_t)HID * HID], g_w3l[(size_t)HID * HID];
__device__ h16 g_t1h[(size_t)MALL * HID], g_t1l[(size_t)MALL * HID];
__device__ h16 g_t2h[(size_t)MALL * HID], g_t2l[(size_t)MALL * HID];
__device__ h16 g_fh[(size_t)MALL * HID], g_fl[(size_t)MALL * HID];  // fa | fb
__device__ h16 g_x1t[(size_t)BATCH * EMB * LA];
__device__ h16 g_x2t[(size_t)BATCH * EMB * LB];
__device__ float g_S[(size_t)BATCH * LA * LB];
__device__ h16 g_pr[(size_t)BATCH * LA * LB];   // row-softmax(S)
__device__ h16 g_pc[(size_t)BATCH * LB * LA];   // col-softmax(S)^T
__device__ float g_mcol[BATCH * LB], g_izcol[BATCH * LB];

// ---------------- ptx helpers ------------------------------------------------
__device__ __forceinline__ uint32_t smem_u32(const void* p) {
  uint32_t a;
  asm("{ .reg .u64 t; cvta.to.shared.u64 t, %1; cvt.u32.u64 %0, t; }"
      : "=r"(a) : "l"(p));
  return a;
}
__device__ __forceinline__ void cp16(uint32_t d, const void* s) {
  asm volatile("cp.async.cg.shared.global [%0], [%1], 16;" :: "r"(d), "l"(s));
}
__device__ __forceinline__ void cp_commit() {
  asm volatile("cp.async.commit_group;");
}
template <int N>
__device__ __forceinline__ void cp_wait() {
  asm volatile("cp.async.wait_group %0;" :: "n"(N));
}
__device__ __forceinline__ void ldsm4(uint32_t* r, uint32_t a) {
  asm volatile("ldmatrix.sync.aligned.m8n8.x4.shared.b16 {%0,%1,%2,%3}, [%4];"
               : "=r"(r[0]), "=r"(r[1]), "=r"(r[2]), "=r"(r[3]) : "r"(a));
}
__device__ __forceinline__ void mma16816(float* d, const uint32_t* a, const uint32_t* b) {
  asm volatile(
      "mma.sync.aligned.m16n8k16.row.col.f32.f16.f16.f32 "
      "{%0,%1,%2,%3}, {%4,%5,%6,%7}, {%8,%9}, {%0,%1,%2,%3};"
      : "+f"(d[0]), "+f"(d[1]), "+f"(d[2]), "+f"(d[3])
      : "r"(a[0]), "r"(a[1]), "r"(a[2]), "r"(a[3]), "r"(b[0]), "r"(b[1]));
}

__device__ __forceinline__ void split_store(h16* oh, h16* ol, size_t o, float v) {
  h16 h = __float2half_rn(v);
  oh[o] = h;
  ol[o] = __float2half_rn(v - __half2float(h));
}
__device__ __forceinline__ void split2_store(h16* oh, h16* ol, size_t o,
                                             float v0, float v1) {
  h16 h0 = __float2half_rn(v0), h1 = __float2half_rn(v1);
  __half2 hp; hp.x = h0; hp.y = h1;
  __half2 lp;
  lp.x = __float2half_rn(v0 - __half2float(h0));
  lp.y = __float2half_rn(v1 - __half2float(h1));
  *(__half2*)(oh + o) = hp;
  *(__half2*)(ol + o) = lp;
}

// ---------------- mma.sync GEMM core: C[128x256] = A @ B^T -------------------
// PASSES=3: A pair, B pair (AhBh + AhBl + AlBh).
// PASSES=2: A pair, B single (AhBh + AlBh).
// PASSES=1: A single, B single (AhBh).
// EPI 0: fp32 C. EPI 1: bias+relu -> fp16 pair.
static constexpr int LDM = 80;        // smem bytes per 32-h16 row (padded)
static constexpr int TAg = 128 * LDM; // 10240
static constexpr int TBg = 256 * LDM; // 20480
static constexpr int SMEM3 = 2 * (2 * TAg + 2 * TBg);  // 122880
static constexpr int SMEM2 = 2 * (2 * TAg + TBg);      // 81920
static constexpr int SMEM1 = 2 * (TAg + TBg);          // 61440

template <int EPI, int PASSES>
__device__ __forceinline__ void gemm_core(
    const h16* __restrict__ Ah, const h16* __restrict__ Al,
    const h16* __restrict__ Bh, const h16* __restrict__ Bl,
    int K, float* __restrict__ C, h16* __restrict__ Oh, h16* __restrict__ Ol,
    const float* __restrict__ bias, int ldc) {
  constexpr int NTA = (PASSES >= 2) ? 2 : 1;
  constexpr int NTB = (PASSES == 3) ? 2 : 1;
  constexpr int STG = NTA * TAg + NTB * TBg;
  extern __shared__ char smem[];
  const uint32_t sb = smem_u32(smem);
  const int tid = threadIdx.x;
  const int lane = tid & 31;
  const int wm = (tid >> 5) >> 2;   // 0..1
  const int wn = (tid >> 5) & 3;    // 0..3
  const size_t bm = (size_t)blockIdx.y * 128, bn = (size_t)blockIdx.x * 256;

  // loader rows
  const h16* p0;
  uint32_t s0;
  if (PASSES >= 2) {
    p0 = (tid < 128) ? Ah + (bm + tid) * (size_t)K
                     : Al + (bm + tid - 128) * (size_t)K;
    s0 = sb + (uint32_t)((tid < 128) ? tid * LDM : TAg + (tid - 128) * LDM);
  } else {
    p0 = Ah + (bm + (tid & 127)) * (size_t)K;   // only tid<128 stores
    s0 = sb + (uint32_t)((tid & 127) * LDM);
  }
  const h16* p1 = Bh + (bn + tid) * (size_t)K;
  const h16* p2 = (PASSES == 3) ? Bl + (bn + tid) * (size_t)K : nullptr;
  const uint32_t s1 = sb + (uint32_t)(NTA * TAg + tid * LDM);
  const uint32_t s2 = sb + (uint32_t)(NTA * TAg + TBg + tid * LDM);

#define LOADST(c, s)                                                     \
  do {                                                                   \
    const uint32_t so_ = (uint32_t)(s) * STG;                            \
    const size_t ko_ = (size_t)(c) * 32;                                 \
    if (PASSES >= 2 || tid < 128)                                        \
      _Pragma("unroll") for (int ch_ = 0; ch_ < 4; ch_++)                \
          cp16(s0 + so_ + ch_ * 16, p0 + ko_ + ch_ * 8);                 \
    _Pragma("unroll") for (int ch_ = 0; ch_ < 4; ch_++)                  \
        cp16(s1 + so_ + ch_ * 16, p1 + ko_ + ch_ * 8);                   \
    if (PASSES == 3)                                                     \
      _Pragma("unroll") for (int ch_ = 0; ch_ < 4; ch_++)                \
          cp16(s2 + so_ + ch_ * 16, p2 + ko_ + ch_ * 8);                 \
    cp_commit();                                                         \
  } while (0)

  // fragment smem addresses (stage 0, kstep 0)
  uint32_t aAh[4], aAl[4], aBh[4], aBl[4];
#pragma unroll
  for (int i = 0; i < 4; i++) {
    int row = wm * 64 + i * 16 + (lane & 15);
    uint32_t off = (uint32_t)(row * LDM + (lane >> 4) * 16);
    aAh[i] = sb + off;
    aAl[i] = sb + TAg + off;
  }
#pragma unroll
  for (int j = 0; j < 4; j++) {
    int row = wn * 64 + j * 16 + (lane & 7) + ((lane >> 4) & 1) * 8;
    uint32_t off = (uint32_t)(row * LDM + ((lane >> 3) & 1) * 16);
    aBh[j] = sb + NTA * TAg + off;
    aBl[j] = sb + NTA * TAg + TBg + off;
  }

  float acc[4][8][4];
#pragma unroll
  for (int i = 0; i < 4; i++)
#pragma unroll
    for (int j = 0; j < 8; j++)
#pragma unroll
      for (int r = 0; r < 4; r++) acc[i][j][r] = 0.f;

  const int NC = K >> 5;
  LOADST(0, 0);
  for (int c = 0; c < NC; c++) {
    const int s = c & 1;
    if (c + 1 < NC) { LOADST(c + 1, s ^ 1); cp_wait<1>(); }
    else            { cp_wait<0>(); }
    __syncthreads();
#pragma unroll
    for (int ks = 0; ks < 2; ks++) {
      const uint32_t soff = (uint32_t)s * STG + ks * 32;
      uint32_t fAh[4][4], fAl[4][4];
#pragma unroll
      for (int i = 0; i < 4; i++) {
        ldsm4(fAh[i], aAh[i] + soff);
        if (PASSES >= 2) ldsm4(fAl[i], aAl[i] + soff);
      }
#pragma unroll
      for (int j = 0; j < 4; j++) {
        uint32_t fBh[4], fBl[4];
        ldsm4(fBh, aBh[j] + soff);
        if (PASSES == 3) ldsm4(fBl, aBl[j] + soff);
#pragma unroll
        for (int i = 0; i < 4; i++)
#pragma unroll
          for (int hh = 0; hh < 2; hh++) {
            float* d = acc[i][j * 2 + hh];
            mma16816(d, fAh[i], &fBh[hh * 2]);
            if (PASSES == 3) mma16816(d, fAh[i], &fBl[hh * 2]);
            if (PASSES >= 2) mma16816(d, fAl[i], &fBh[hh * 2]);
          }
      }
    }
    __syncthreads();
  }
#undef LOADST

  // epilogue
  const int l4 = lane >> 2, l2 = (lane & 3) * 2;
#pragma unroll
  for (int i = 0; i < 4; i++) {
#pragma unroll
    for (int j = 0; j < 8; j++) {
      const size_t row = bm + wm * 64 + i * 16 + l4;
      const size_t col = bn + wn * 64 + j * 8 + l2;
      float* a = acc[i][j];
      const size_t o = row * (size_t)ldc + col;
      if (EPI == 0) {
        float2 v0; v0.x = a[0]; v0.y = a[1];
        float2 v1; v1.x = a[2]; v1.y = a[3];
        *(float2*)(C + o) = v0;
        *(float2*)(C + o + 8 * (size_t)ldc) = v1;
      } else {
        float2 bv = *(const float2*)(bias + col);
        split2_store(Oh, Ol, o, fmaxf(a[0] + bv.x, 0.f), fmaxf(a[1] + bv.y, 0.f));
        split2_store(Oh, Ol, o + 8 * (size_t)ldc,
                     fmaxf(a[2] + bv.x, 0.f), fmaxf(a[3] + bv.y, 0.f));
      }
    }
  }
}

// generic wrapper (per-batch strides)
template <int EPI, int PASSES>
__global__ void __launch_bounds__(256, 1) gemm_mma(
    const h16* Ah, const h16* Al, const h16* Bh, const h16* Bl,
    int K, long long sA, long long sB,
    float* C, h16* Oh, h16* Ol, const float* bias, long long sC, int ldc) {
  const size_t b = blockIdx.z;
  gemm_core<EPI, PASSES>(
      Ah + b * sA, (PASSES >= 2) ? Al + b * sA : nullptr, Bh + b * sB,
      (PASSES == 3) ? Bl + b * sB : nullptr, K,
      (EPI == 0) ? C + b * sC : nullptr,
      (EPI == 1) ? Oh + b * sC : nullptr,
      (EPI == 1) ? Ol + b * sC : nullptr, bias, ldc);
}

// fused beta+alpha, 1-pass: z=0,1 -> beta batches; z=2,3 -> alpha batches
__global__ void __launch_bounds__(256, 1) attn_fused(
    const h16* __restrict__ x2t, const h16* __restrict__ x1t,
    float* __restrict__ beta, float* __restrict__ alpha) {
  const int z = blockIdx.z;
  const h16 *A, *Bh;
  float* C;
  if (z < 2) {
    A = g_pr + (size_t)z * LA * LB;
    Bh = x2t + (size_t)z * EMB * LB;
    C = beta + (size_t)z * LA * EMB;
  } else {
    const int b = z - 2;
    A = g_pc + (size_t)b * LB * LA;
    Bh = x1t + (size_t)b * EMB * LA;
    C = alpha + (size_t)b * LB * EMB;
  }
  gemm_core<0, 1>(A, nullptr, Bh, nullptr, LB, C, nullptr, nullptr, nullptr, EMB);
}

// ---------------- conversion kernels -----------------------------------------
// fused: x -> (hi,lo) row-major pair AND transposed fp16, single read of x.
// in: [B, L, E]; oh/ol: flat rows [(base+b*L)..] x E; ot: [B, E, L]
__global__ void k_prep(const float* __restrict__ in, h16* __restrict__ oh,
                       h16* __restrict__ ol, h16* __restrict__ ot, int L) {
  __shared__ float t[32][33];
  const int b = blockIdx.z;
  const int r0 = blockIdx.y * 32, c0 = blockIdx.x * 32;  // r: L dim, c: E dim
  const int tx = threadIdx.x, ty = threadIdx.y;
  const float* pin = in + (size_t)b * L * EMB;
#pragma unroll
  for (int k = 0; k < 4; k++) {
    const int r = r0 + ty + 8 * k;
    float v = pin[(size_t)r * EMB + c0 + tx];
    t[ty + 8 * k][tx] = v;
    split_store(oh, ol, (size_t)(b * L + r) * EMB + c0 + tx, v);
  }
  __syncthreads();
#pragma unroll
  for (int k = 0; k < 4; k++) {
    size_t o = (size_t)b * EMB * L + (size_t)(c0 + ty + 8 * k) * L + r0 + tx;
    ot[o] = __float2half_rn(t[tx][ty + 8 * k]);
  }
}

__global__ void k_tsplit(const float* __restrict__ in, h16* __restrict__ oh,
                         h16* __restrict__ ol, int R, int Cc) {
  __shared__ float t[32][33];
  const int r0 = blockIdx.y * 32, c0 = blockIdx.x * 32;
  const int tx = threadIdx.x, ty = threadIdx.y;
#pragma unroll
  for (int k = 0; k < 4; k++)
    t[ty + 8 * k][tx] = in[(size_t)(r0 + ty + 8 * k) * Cc + c0 + tx];
  __syncthreads();
#pragma unroll
  for (int k = 0; k < 4; k++) {
    float v = t[tx][ty + 8 * k];
    size_t o = (size_t)(c0 + ty + 8 * k) * R + r0 + tx;
    split_store(oh, ol, o, v);
  }
}

// ---------------- softmax -----------------------------------------------------
__device__ __forceinline__ void olcomb(float& m, float& z, float m2, float z2) {
  if (m2 > m) { z = z * __expf(m - m2) + z2; m = m2; }
  else        { z = z + z2 * __expf(m2 - m); }
}

// fused: row stats + exp-normalize -> g_pr (fp16)
__global__ void row_softmax_kernel() {
  const int row = blockIdx.x;
  const float* s = g_S + (size_t)row * LB;
  float m = -3.0e38f, z = 0.f;
  for (int j = threadIdx.x; j < LB; j += 256) {
    float v = s[j];
    if (v > m) { z = z * __expf(m - v) + 1.f; m = v; }
    else       { z += __expf(v - m); }
  }
  __shared__ float sm[256], sz[256];
  sm[threadIdx.x] = m; sz[threadIdx.x] = z;
  __syncthreads();
  for (int st = 128; st > 0; st >>= 1) {
    if (threadIdx.x < st) {
      float m1 = sm[threadIdx.x], z1 = sz[threadIdx.x];
      olcomb(m1, z1, sm[threadIdx.x + st], sz[threadIdx.x + st]);
      sm[threadIdx.x] = m1; sz[threadIdx.x] = z1;
    }
    __syncthreads();
  }
  const float mm = sm[0], iz = 1.f / sz[0];
  h16* p = g_pr + (size_t)row * LB;
  for (int j = threadIdx.x; j < LB; j += 256)
    p[j] = __float2half_rn(__expf(s[j] - mm) * iz);
}

__global__ void col_stats_kernel() {
  const int b = blockIdx.y;
  const int col = blockIdx.x * 128 + threadIdx.x;
  const float* s = g_S + (size_t)b * LA * LB + col;
  float m = -3.0e38f, z = 0.f;
  for (int i = threadIdx.y; i < LA; i += 8) {
    float v = s[(size_t)i * LB];
    if (v > m) { z = z * __expf(m - v) + 1.f; m = v; }
    else       { z += __expf(v - m); }
  }
  __shared__ float sm[8][128], sz[8][128];
  sm[threadIdx.y][threadIdx.x] = m; sz[threadIdx.y][threadIdx.x] = z;
  __syncthreads();
  if (threadIdx.y == 0) {
#pragma unroll
    for (int y = 1; y < 8; y++) olcomb(m, z, sm[y][threadIdx.x], sz[y][threadIdx.x]);
    g_mcol[b * LB + col] = m;
    g_izcol[b * LB + col] = 1.f / z;
  }
}

// col-softmax + transpose -> g_pc (fp16)
__global__ void k_pcolT() {
  __shared__ float t[32][33];
  const int b = blockIdx.z;
  const int i0 = blockIdx.y * 32, j0 = blockIdx.x * 32;
  const int tx = threadIdx.x, ty = threadIdx.y;
  const float* S = g_S + (size_t)b * LA * LB;
#pragma unroll
  for (int k = 0; k < 4; k++)
    t[ty + 8 * k][tx] = S[(size_t)(i0 + ty + 8 * k) * LB + j0 + tx];
  __syncthreads();
#pragma unroll
  for (int k = 0; k < 4; k++) {
    const int j = j0 + ty + 8 * k;
    float p = __expf(t[tx][ty + 8 * k] - g_mcol[b * LB + j]) * g_izcol[b * LB + j];
    size_t o = (size_t)b * LB * LA + (size_t)j * LA + i0 + tx;
    g_pc[o] = __float2half_rn(p);
  }
}

// ---------------- launch -----------------------------------------------------
#define GSA(T, v, sym) T* v; cudaGetSymbolAddress((void**)&v, sym)

extern "C" void kernel_launch(void* const* d_in, const int* in_sizes, int n_in,
                              void* d_out, int out_size) {
  const float* x1 = (const float*)d_in[0];
  const float* x2 = (const float*)d_in[1];
  const float* W1 = (const float*)d_in[2];
  const float* b1 = (const float*)d_in[3];
  const float* W2 = (const float*)d_in[4];
  const float* b2 = (const float*)d_in[5];
  const float* W3 = (const float*)d_in[6];
  const float* b3 = (const float*)d_in[7];
  float* out = (float*)d_out;
  float* alpha_out = out;                             // [B, LB, EMB]
  float* beta_out = out + (size_t)BATCH * LB * EMB;   // [B, LA, EMB]

  GSA(h16, xh, g_xh); GSA(h16, xl, g_xl);
  GSA(h16, w1h, g_w1h); GSA(h16, w1l, g_w1l);
  GSA(h16, w2h, g_w2h); GSA(h16, w2l, g_w2l);
  GSA(h16, w3h, g_w3h); GSA(h16, w3l, g_w3l);
  GSA(h16, t1h, g_t1h); GSA(h16, t1l, g_t1l);
  GSA(h16, t2h, g_t2h); GSA(h16, t2l, g_t2l);
  GSA(h16, fh, g_fh); GSA(h16, fl, g_fl);
  GSA(h16, x1t, g_x1t); GSA(h16, x2t, g_x2t);
  GSA(float, S, g_S);

  cudaFuncSetAttribute(gemm_mma<0, 3>, cudaFuncAttributeMaxDynamicSharedMemorySize, SMEM3);
  cudaFuncSetAttribute(gemm_mma<1, 3>, cudaFuncAttributeMaxDynamicSharedMemorySize, SMEM3);
  cudaFuncSetAttribute(gemm_mma<0, 2>, cudaFuncAttributeMaxDynamicSharedMemorySize, SMEM2);
  cudaFuncSetAttribute(attn_fused, cudaFuncAttributeMaxDynamicSharedMemorySize, SMEM1);

  const size_t nx = (size_t)MTOT * EMB;
  dim3 t8(32, 8);

  // fused input prep: x1 -> rows [0, 8192) + x1t ; x2 -> rows [8192, 16384) + x2t
  k_prep<<<dim3(EMB / 32, LA / 32, BATCH), t8>>>(x1, xh, xl, x1t, LA);
  k_prep<<<dim3(EMB / 32, LB / 32, BATCH), t8>>>(x2, xh + nx, xl + nx, x2t, LB);
  k_tsplit<<<dim3(HID / 32, EMB / 32), t8>>>(W1, w1h, w1l, EMB, HID);
  k_tsplit<<<dim3(HID / 32, HID / 32), t8>>>(W2, w2h, w2l, HID, HID);
  k_tsplit<<<dim3(HID / 32, HID / 32), t8>>>(W3, w3h, w3l, HID, HID);

  // merged MLP (both inputs, both batches): M = 16384, 3-pass
  dim3 gMLP(HID / 256, MALL / 128, 1);  // (4, 128)
  gemm_mma<1, 3><<<gMLP, 256, SMEM3>>>(xh, xl, w1h, w1l, EMB, 0, 0,
                                       nullptr, t1h, t1l, b1, 0, HID);
  gemm_mma<1, 3><<<gMLP, 256, SMEM3>>>(t1h, t1l, w2h, w2l, HID, 0, 0,
                                       nullptr, t2h, t2l, b2, 0, HID);
  gemm_mma<1, 3><<<gMLP, 256, SMEM3>>>(t2h, t2l, w3h, w3l, HID, 0, 0,
                                       nullptr, fh, fl, b3, 0, HID);

  // scores: S[b] = fa[b] @ fb[b]^T, 2-pass (AhBh + AlBh)
  const h16* fah = fh;
  const h16* fal = fl;
  const h16* fbh = fh + (size_t)MTOT * HID;
  gemm_mma<0, 2><<<dim3(LB / 256, LA / 128, BATCH), 256, SMEM2>>>(
      fah, fal, fbh, nullptr, HID, (long long)LA * HID, (long long)LB * HID,
      S, nullptr, nullptr, nullptr, (long long)LA * LB, LB);

  // softmax: fused row stats+normalize; col stats then transpose-normalize
  row_softmax_kernel<<<BATCH * LA, 256>>>();
  col_stats_kernel<<<dim3(LB / 128, BATCH), dim3(128, 8)>>>();
  k_pcolT<<<dim3(LB / 32, LA / 32, BATCH), t8>>>();

  // fused beta+alpha (1-pass): z=0,1 beta; z=2,3 alpha
  attn_fused<<<dim3(EMB / 256, LA / 128, 4), 256, SMEM1>>>(
      x2t, x1t, beta_out, alpha_out);
}

// round 9
// speedup vs baseline: 2.6978x; 1.0382x over previous
#include <cuda_runtime.h>
#include <cuda_fp16.h>
#include <stdint.h>
#include <math.h>

#define BATCH 2
#define LA 4096
#define LB 4096
#define EMB 1024
#define HID 1024
#define MTOT (BATCH * LA)
#define MALL (2 * MTOT)   // both MLPs merged: 16384 rows

typedef __half h16;

// ---------------- scratch (device globals: no alloc allowed) ----------------
__device__ h16 g_xh[(size_t)MALL * EMB], g_xl[(size_t)MALL * EMB];
__device__ h16 g_w1h[(size_t)HID * EMB], g_w1l[(size_t)HID * EMB];
__device__ h16 g_w2h[(size_t)HID * HID], g_w2l[(size_t)HID * HID];
__device__ h16 g_w3h[(size_t)HID * HID], g_w3l[(size_t)HID * HID];
__device__ h16 g_t1h[(size_t)MALL * HID], g_t1l[(size_t)MALL * HID];
__device__ h16 g_t2h[(size_t)MALL * HID], g_t2l[(size_t)MALL * HID];
__device__ h16 g_fh[(size_t)MALL * HID], g_fl[(size_t)MALL * HID];  // fa | fb
__device__ h16 g_x1t[(size_t)BATCH * EMB * LA];
__device__ h16 g_x2t[(size_t)BATCH * EMB * LB];
__device__ float g_S[(size_t)BATCH * LA * LB];
__device__ h16 g_pr[(size_t)BATCH * LA * LB];   // row-softmax(S)
__device__ h16 g_pc[(size_t)BATCH * LB * LA];   // col-softmax(S)^T
__device__ float g_mcol[BATCH * LB], g_izcol[BATCH * LB];

// ---------------- ptx helpers ------------------------------------------------
__device__ __forceinline__ uint32_t smem_u32(const void* p) {
  uint32_t a;
  asm("{ .reg .u64 t; cvta.to.shared.u64 t, %1; cvt.u32.u64 %0, t; }"
      : "=r"(a) : "l"(p));
  return a;
}
__device__ __forceinline__ void cp16(uint32_t d, const void* s) {
  asm volatile("cp.async.cg.shared.global [%0], [%1], 16;" :: "r"(d), "l"(s));
}
__device__ __forceinline__ void cp_commit() {
  asm volatile("cp.async.commit_group;");
}
template <int N>
__device__ __forceinline__ void cp_wait() {
  asm volatile("cp.async.wait_group %0;" :: "n"(N));
}
__device__ __forceinline__ void ldsm4(uint32_t* r, uint32_t a) {
  asm volatile("ldmatrix.sync.aligned.m8n8.x4.shared.b16 {%0,%1,%2,%3}, [%4];"
               : "=r"(r[0]), "=r"(r[1]), "=r"(r[2]), "=r"(r[3]) : "r"(a));
}
__device__ __forceinline__ void mma16816(float* d, const uint32_t* a, const uint32_t* b) {
  asm volatile(
      "mma.sync.aligned.m16n8k16.row.col.f32.f16.f16.f32 "
      "{%0,%1,%2,%3}, {%4,%5,%6,%7}, {%8,%9}, {%0,%1,%2,%3};"
      : "+f"(d[0]), "+f"(d[1]), "+f"(d[2]), "+f"(d[3])
      : "r"(a[0]), "r"(a[1]), "r"(a[2]), "r"(a[3]), "r"(b[0]), "r"(b[1]));
}

__device__ __forceinline__ void split_store(h16* oh, h16* ol, size_t o, float v) {
  h16 h = __float2half_rn(v);
  oh[o] = h;
  ol[o] = __float2half_rn(v - __half2float(h));
}
__device__ __forceinline__ void split2_store(h16* oh, h16* ol, size_t o,
                                             float v0, float v1) {
  h16 h0 = __float2half_rn(v0), h1 = __float2half_rn(v1);
  __half2 hp; hp.x = h0; hp.y = h1;
  __half2 lp;
  lp.x = __float2half_rn(v0 - __half2float(h0));
  lp.y = __float2half_rn(v1 - __half2float(h1));
  *(__half2*)(oh + o) = hp;
  *(__half2*)(ol + o) = lp;
}

// ---------------- mma.sync GEMM core: C[128x256] = A @ B^T -------------------
// PASSES=3: A pair, B pair (AhBh + AhBl + AlBh).
// PASSES=2: A pair, B single (AhBh + AlBh).
// PASSES=1: A single, B single (AhBh).
// 3-stage cp.async pipeline, ONE __syncthreads per k-chunk.
static constexpr int LDM = 80;        // smem bytes per 32-h16 row (padded)
static constexpr int TAg = 128 * LDM; // 10240
static constexpr int TBg = 256 * LDM; // 20480
static constexpr int SMEM3 = 3 * (2 * TAg + 2 * TBg);  // 184320
static constexpr int SMEM2 = 3 * (2 * TAg + TBg);      // 122880
static constexpr int SMEM1 = 3 * (TAg + TBg);          // 92160

template <int EPI, int PASSES>
__device__ __forceinline__ void gemm_core(
    const h16* __restrict__ Ah, const h16* __restrict__ Al,
    const h16* __restrict__ Bh, const h16* __restrict__ Bl,
    int K, float* __restrict__ C, h16* __restrict__ Oh, h16* __restrict__ Ol,
    const float* __restrict__ bias, int ldc) {
  constexpr int NTA = (PASSES >= 2) ? 2 : 1;
  constexpr int NTB = (PASSES == 3) ? 2 : 1;
  constexpr int STG = NTA * TAg + NTB * TBg;
  extern __shared__ char smem[];
  const uint32_t sb = smem_u32(smem);
  const int tid = threadIdx.x;
  const int lane = tid & 31;
  const int wm = (tid >> 5) >> 2;   // 0..1
  const int wn = (tid >> 5) & 3;    // 0..3
  const size_t bm = (size_t)blockIdx.y * 128, bn = (size_t)blockIdx.x * 256;

  // loader rows
  const h16* p0;
  uint32_t s0;
  if (PASSES >= 2) {
    p0 = (tid < 128) ? Ah + (bm + tid) * (size_t)K
                     : Al + (bm + tid - 128) * (size_t)K;
    s0 = sb + (uint32_t)((tid < 128) ? tid * LDM : TAg + (tid - 128) * LDM);
  } else {
    p0 = Ah + (bm + (tid & 127)) * (size_t)K;   // only tid<128 stores
    s0 = sb + (uint32_t)((tid & 127) * LDM);
  }
  const h16* p1 = Bh + (bn + tid) * (size_t)K;
  const h16* p2 = (PASSES == 3) ? Bl + (bn + tid) * (size_t)K : nullptr;
  const uint32_t s1 = sb + (uint32_t)(NTA * TAg + tid * LDM);
  const uint32_t s2 = sb + (uint32_t)(NTA * TAg + TBg + tid * LDM);

#define LOADST(c, s)                                                     \
  do {                                                                   \
    const uint32_t so_ = (uint32_t)(s) * STG;                            \
    const size_t ko_ = (size_t)(c) * 32;                                 \
    if (PASSES >= 2 || tid < 128)                                        \
      _Pragma("unroll") for (int ch_ = 0; ch_ < 4; ch_++)                \
          cp16(s0 + so_ + ch_ * 16, p0 + ko_ + ch_ * 8);                 \
    _Pragma("unroll") for (int ch_ = 0; ch_ < 4; ch_++)                  \
        cp16(s1 + so_ + ch_ * 16, p1 + ko_ + ch_ * 8);                   \
    if (PASSES == 3)                                                     \
      _Pragma("unroll") for (int ch_ = 0; ch_ < 4; ch_++)                \
          cp16(s2 + so_ + ch_ * 16, p2 + ko_ + ch_ * 8);                 \
    cp_commit();                                                         \
  } while (0)

  // fragment smem addresses (stage 0, kstep 0)
  uint32_t aAh[4], aAl[4], aBh[4], aBl[4];
#pragma unroll
  for (int i = 0; i < 4; i++) {
    int row = wm * 64 + i * 16 + (lane & 15);
    uint32_t off = (uint32_t)(row * LDM + (lane >> 4) * 16);
    aAh[i] = sb + off;
    aAl[i] = sb + TAg + off;
  }
#pragma unroll
  for (int j = 0; j < 4; j++) {
    int row = wn * 64 + j * 16 + (lane & 7) + ((lane >> 4) & 1) * 8;
    uint32_t off = (uint32_t)(row * LDM + ((lane >> 3) & 1) * 16);
    aBh[j] = sb + NTA * TAg + off;
    aBl[j] = sb + NTA * TAg + TBg + off;
  }

  float acc[4][8][4];
#pragma unroll
  for (int i = 0; i < 4; i++)
#pragma unroll
    for (int j = 0; j < 8; j++)
#pragma unroll
      for (int r = 0; r < 4; r++) acc[i][j][r] = 0.f;

  const int NC = K >> 5;
  LOADST(0, 0);
  LOADST(1, 1);
  for (int c = 0; c < NC; c++) {
    if (c + 1 < NC) cp_wait<1>(); else cp_wait<0>();
    __syncthreads();
    if (c + 2 < NC) LOADST(c + 2, (c + 2) % 3);
    const uint32_t sbase = (uint32_t)(c % 3) * STG;
#pragma unroll
    for (int ks = 0; ks < 2; ks++) {
      const uint32_t soff = sbase + ks * 32;
      uint32_t fAh[4][4], fAl[4][4];
#pragma unroll
      for (int i = 0; i < 4; i++) {
        ldsm4(fAh[i], aAh[i] + soff);
        if (PASSES >= 2) ldsm4(fAl[i], aAl[i] + soff);
      }
#pragma unroll
      for (int j = 0; j < 4; j++) {
        uint32_t fBh[4], fBl[4];
        ldsm4(fBh, aBh[j] + soff);
        if (PASSES == 3) ldsm4(fBl, aBl[j] + soff);
#pragma unroll
        for (int i = 0; i < 4; i++)
#pragma unroll
          for (int hh = 0; hh < 2; hh++) {
            float* d = acc[i][j * 2 + hh];
            mma16816(d, fAh[i], &fBh[hh * 2]);
            if (PASSES == 3) mma16816(d, fAh[i], &fBl[hh * 2]);
            if (PASSES >= 2) mma16816(d, fAl[i], &fBh[hh * 2]);
          }
      }
    }
  }
#undef LOADST

  // epilogue
  const int l4 = lane >> 2, l2 = (lane & 3) * 2;
#pragma unroll
  for (int i = 0; i < 4; i++) {
#pragma unroll
    for (int j = 0; j < 8; j++) {
      const size_t row = bm + wm * 64 + i * 16 + l4;
      const size_t col = bn + wn * 64 + j * 8 + l2;
      float* a = acc[i][j];
      const size_t o = row * (size_t)ldc + col;
      if (EPI == 0) {
        float2 v0; v0.x = a[0]; v0.y = a[1];
        float2 v1; v1.x = a[2]; v1.y = a[3];
        *(float2*)(C + o) = v0;
        *(float2*)(C + o + 8 * (size_t)ldc) = v1;
      } else {
        float2 bv = *(const float2*)(bias + col);
        split2_store(Oh, Ol, o, fmaxf(a[0] + bv.x, 0.f), fmaxf(a[1] + bv.y, 0.f));
        split2_store(Oh, Ol, o + 8 * (size_t)ldc,
                     fmaxf(a[2] + bv.x, 0.f), fmaxf(a[3] + bv.y, 0.f));
      }
    }
  }
}

// generic wrapper (per-batch strides)
template <int EPI, int PASSES>
__global__ void __launch_bounds__(256, 1) gemm_mma(
    const h16* Ah, const h16* Al, const h16* Bh, const h16* Bl,
    int K, long long sA, long long sB,
    float* C, h16* Oh, h16* Ol, const float* bias, long long sC, int ldc) {
  const size_t b = blockIdx.z;
  gemm_core<EPI, PASSES>(
      Ah + b * sA, (PASSES >= 2) ? Al + b * sA : nullptr, Bh + b * sB,
      (PASSES == 3) ? Bl + b * sB : nullptr, K,
      (EPI == 0) ? C + b * sC : nullptr,
      (EPI == 1) ? Oh + b * sC : nullptr,
      (EPI == 1) ? Ol + b * sC : nullptr, bias, ldc);
}

// fused beta+alpha, 1-pass: z=0,1 -> beta batches; z=2,3 -> alpha batches
__global__ void __launch_bounds__(256, 1) attn_fused(
    const h16* __restrict__ x2t, const h16* __restrict__ x1t,
    float* __restrict__ beta, float* __restrict__ alpha) {
  const int z = blockIdx.z;
  const h16 *A, *Bh;
  float* C;
  if (z < 2) {
    A = g_pr + (size_t)z * LA * LB;
    Bh = x2t + (size_t)z * EMB * LB;
    C = beta + (size_t)z * LA * EMB;
  } else {
    const int b = z - 2;
    A = g_pc + (size_t)b * LB * LA;
    Bh = x1t + (size_t)b * EMB * LA;
    C = alpha + (size_t)b * LB * EMB;
  }
  gemm_core<0, 1>(A, nullptr, Bh, nullptr, LB, C, nullptr, nullptr, nullptr, EMB);
}

// ---------------- conversion kernels -----------------------------------------
// fused: x -> (hi,lo) row-major pair AND transposed fp16, single read of x.
// block (32,8); tile 64 rows (L dim) x 32 cols (E dim).
__global__ void k_prep(const float* __restrict__ in, h16* __restrict__ oh,
                       h16* __restrict__ ol, h16* __restrict__ ot, int L) {
  __shared__ float t[64][33];
  const int b = blockIdx.z;
  const int r0 = blockIdx.y * 64, c0 = blockIdx.x * 32;
  const int tx = threadIdx.x, ty = threadIdx.y;
  const float* pin = in + (size_t)b * L * EMB;
#pragma unroll
  for (int k = 0; k < 8; k++) {
    const int r = r0 + ty + 8 * k;
    float v = pin[(size_t)r * EMB + c0 + tx];
    t[ty + 8 * k][tx] = v;
    split_store(oh, ol, (size_t)(b * L + r) * EMB + c0 + tx, v);
  }
  __syncthreads();
#pragma unroll
  for (int k = 0; k < 4; k++) {
    const int c = c0 + ty + 8 * k;
    __half2 h = __floats2half2_rn(t[2 * tx][ty + 8 * k], t[2 * tx + 1][ty + 8 * k]);
    *(__half2*)(ot + (size_t)b * EMB * L + (size_t)c * L + r0 + 2 * tx) = h;
  }
}

__global__ void k_tsplit(const float* __restrict__ in, h16* __restrict__ oh,
                         h16* __restrict__ ol, int R, int Cc) {
  __shared__ float t[32][33];
  const int r0 = blockIdx.y * 32, c0 = blockIdx.x * 32;
  const int tx = threadIdx.x, ty = threadIdx.y;
#pragma unroll
  for (int k = 0; k < 4; k++)
    t[ty + 8 * k][tx] = in[(size_t)(r0 + ty + 8 * k) * Cc + c0 + tx];
  __syncthreads();
#pragma unroll
  for (int k = 0; k < 4; k++) {
    float v = t[tx][ty + 8 * k];
    size_t o = (size_t)(c0 + ty + 8 * k) * R + r0 + tx;
    split_store(oh, ol, o, v);
  }
}

// ---------------- softmax -----------------------------------------------------
__device__ __forceinline__ void olcomb(float& m, float& z, float m2, float z2) {
  if (m2 > m) { z = z * __expf(m - m2) + z2; m = m2; }
  else        { z = z + z2 * __expf(m2 - m); }
}
__device__ __forceinline__ void olup(float& m, float& z, float v) {
  if (v > m) { z = z * __expf(m - v) + 1.f; m = v; }
  else       { z += __expf(v - m); }
}

// fused: row stats + exp-normalize -> g_pr (fp16), float4/uint2 vectorized
__global__ void row_softmax_kernel() {
  const int row = blockIdx.x;
  const float4* s4 = (const float4*)(g_S + (size_t)row * LB);
  float m = -3.0e38f, z = 0.f;
  for (int j = threadIdx.x; j < LB / 4; j += 256) {
    float4 v = s4[j];
    olup(m, z, v.x); olup(m, z, v.y); olup(m, z, v.z); olup(m, z, v.w);
  }
  __shared__ float sm[256], sz[256];
  sm[threadIdx.x] = m; sz[threadIdx.x] = z;
  __syncthreads();
  for (int st = 128; st > 0; st >>= 1) {
    if (threadIdx.x < st) {
      float m1 = sm[threadIdx.x], z1 = sz[threadIdx.x];
      olcomb(m1, z1, sm[threadIdx.x + st], sz[threadIdx.x + st]);
      sm[threadIdx.x] = m1; sz[threadIdx.x] = z1;
    }
    __syncthreads();
  }
  const float mm = sm[0], iz = 1.f / sz[0];
  uint2* p = (uint2*)(g_pr + (size_t)row * LB);
  for (int j = threadIdx.x; j < LB / 4; j += 256) {
    float4 v = s4[j];
    __half2 h01 = __floats2half2_rn(__expf(v.x - mm) * iz, __expf(v.y - mm) * iz);
    __half2 h23 = __floats2half2_rn(__expf(v.z - mm) * iz, __expf(v.w - mm) * iz);
    uint2 w;
    w.x = *(uint32_t*)&h01;
    w.y = *(uint32_t*)&h23;
    p[j] = w;
  }
}

__global__ void col_stats_kernel() {
  const int b = blockIdx.y;
  const int col = blockIdx.x * 128 + threadIdx.x;
  const float* s = g_S + (size_t)b * LA * LB + col;
  float m = -3.0e38f, z = 0.f;
  for (int i = threadIdx.y; i < LA; i += 8) {
    float v = s[(size_t)i * LB];
    olup(m, z, v);
  }
  __shared__ float sm[8][128], sz[8][128];
  sm[threadIdx.y][threadIdx.x] = m; sz[threadIdx.y][threadIdx.x] = z;
  __syncthreads();
  if (threadIdx.y == 0) {
#pragma unroll
    for (int y = 1; y < 8; y++) olcomb(m, z, sm[y][threadIdx.x], sz[y][threadIdx.x]);
    g_mcol[b * LB + col] = m;
    g_izcol[b * LB + col] = 1.f / z;
  }
}

// col-softmax + transpose -> g_pc (fp16). block (32,8); tile 64 i x 32 j.
__global__ void k_pcolT() {
  __shared__ float t[64][33];
  const int b = blockIdx.z;
  const int i0 = blockIdx.y * 64, j0 = blockIdx.x * 32;
  const int tx = threadIdx.x, ty = threadIdx.y;
  const float* S = g_S + (size_t)b * LA * LB;
#pragma unroll
  for (int k = 0; k < 8; k++)
    t[ty + 8 * k][tx] = S[(size_t)(i0 + ty + 8 * k) * LB + j0 + tx];
  __syncthreads();
#pragma unroll
  for (int k = 0; k < 4; k++) {
    const int j = j0 + ty + 8 * k;
    const float m = g_mcol[b * LB + j], iz = g_izcol[b * LB + j];
    float p0 = __expf(t[2 * tx][ty + 8 * k] - m) * iz;
    float p1 = __expf(t[2 * tx + 1][ty + 8 * k] - m) * iz;
    __half2 h = __floats2half2_rn(p0, p1);
    *(__half2*)(g_pc + (size_t)b * LB * LA + (size_t)j * LA + i0 + 2 * tx) = h;
  }
}

// ---------------- launch -----------------------------------------------------
#define GSA(T, v, sym) T* v; cudaGetSymbolAddress((void**)&v, sym)

extern "C" void kernel_launch(void* const* d_in, const int* in_sizes, int n_in,
                              void* d_out, int out_size) {
  const float* x1 = (const float*)d_in[0];
  const float* x2 = (const float*)d_in[1];
  const float* W1 = (const float*)d_in[2];
  const float* b1 = (const float*)d_in[3];
  const float* W2 = (const float*)d_in[4];
  const float* b2 = (const float*)d_in[5];
  const float* W3 = (const float*)d_in[6];
  const float* b3 = (const float*)d_in[7];
  float* out = (float*)d_out;
  float* alpha_out = out;                             // [B, LB, EMB]
  float* beta_out = out + (size_t)BATCH * LB * EMB;   // [B, LA, EMB]

  GSA(h16, xh, g_xh); GSA(h16, xl, g_xl);
  GSA(h16, w1h, g_w1h); GSA(h16, w1l, g_w1l);
  GSA(h16, w2h, g_w2h); GSA(h16, w2l, g_w2l);
  GSA(h16, w3h, g_w3h); GSA(h16, w3l, g_w3l);
  GSA(h16, t1h, g_t1h); GSA(h16, t1l, g_t1l);
  GSA(h16, t2h, g_t2h); GSA(h16, t2l, g_t2l);
  GSA(h16, fh, g_fh); GSA(h16, fl, g_fl);
  GSA(h16, x1t, g_x1t); GSA(h16, x2t, g_x2t);
  GSA(float, S, g_S);

  cudaFuncSetAttribute(gemm_mma<0, 3>, cudaFuncAttributeMaxDynamicSharedMemorySize, SMEM3);
  cudaFuncSetAttribute(gemm_mma<1, 3>, cudaFuncAttributeMaxDynamicSharedMemorySize, SMEM3);
  cudaFuncSetAttribute(gemm_mma<0, 2>, cudaFuncAttributeMaxDynamicSharedMemorySize, SMEM2);
  cudaFuncSetAttribute(attn_fused, cudaFuncAttributeMaxDynamicSharedMemorySize, SMEM1);

  const size_t nx = (size_t)MTOT * EMB;
  dim3 t8(32, 8);

  // fused input prep: x1 -> rows [0, 8192) + x1t ; x2 -> rows [8192, 16384) + x2t
  k_prep<<<dim3(EMB / 32, LA / 64, BATCH), t8>>>(x1, xh, xl, x1t, LA);
  k_prep<<<dim3(EMB / 32, LB / 64, BATCH), t8>>>(x2, xh + nx, xl + nx, x2t, LB);
  k_tsplit<<<dim3(HID / 32, EMB / 32), t8>>>(W1, w1h, w1l, EMB, HID);
  k_tsplit<<<dim3(HID / 32, HID / 32), t8>>>(W2, w2h, w2l, HID, HID);
  k_tsplit<<<dim3(HID / 32, HID / 32), t8>>>(W3, w3h, w3l, HID, HID);

  // merged MLP (both inputs, both batches): M = 16384, 3-pass
  dim3 gMLP(HID / 256, MALL / 128, 1);  // (4, 128)
  gemm_mma<1, 3><<<gMLP, 256, SMEM3>>>(xh, xl, w1h, w1l, EMB, 0, 0,
                                       nullptr, t1h, t1l, b1, 0, HID);
  gemm_mma<1, 3><<<gMLP, 256, SMEM3>>>(t1h, t1l, w2h, w2l, HID, 0, 0,
                                       nullptr, t2h, t2l, b2, 0, HID);
  gemm_mma<1, 3><<<gMLP, 256, SMEM3>>>(t2h, t2l, w3h, w3l, HID, 0, 0,
                                       nullptr, fh, fl, b3, 0, HID);

  // scores: S[b] = fa[b] @ fb[b]^T, 2-pass (AhBh + AlBh)
  const h16* fah = fh;
  const h16* fal = fl;
  const h16* fbh = fh + (size_t)MTOT * HID;
  gemm_mma<0, 2><<<dim3(LB / 256, LA / 128, BATCH), 256, SMEM2>>>(
      fah, fal, fbh, nullptr, HID, (long long)LA * HID, (long long)LB * HID,
      S, nullptr, nullptr, nullptr, (long long)LA * LB, LB);

  // softmax: fused row stats+normalize; col stats then transpose-normalize
  row_softmax_kernel<<<BATCH * LA, 256>>>();
  col_stats_kernel<<<dim3(LB / 128, BATCH), dim3(128, 8)>>>();
  k_pcolT<<<dim3(LB / 32, LA / 64, BATCH), t8>>>();

  // fused beta+alpha (1-pass): z=0,1 beta; z=2,3 alpha
  attn_fused<<<dim3(EMB / 256, LA / 128, 4), 256, SMEM1>>>(
      x2t, x1t, beta_out, alpha_out);
}